// round 12
// baseline (speedup 1.0000x reference)
#include <cuda_runtime.h>
#include <cuda_fp16.h>
#include <math.h>

#define U_CNT 8192
#define N_CNT 16384
#define D_DIM 128
#define E_CNT 524288
#define K_TOP 32
#define NCAND 64
#define PAD   132

// ---------------- scratch (device globals; no allocation) ----------------
__device__ float g_bufA[N_CNT * D_DIM];
__device__ float g_bufB[N_CNT * D_DIM];
__device__ float g_ego [N_CNT * D_DIM];
__device__ float g_q   [N_CNT * D_DIM];   // reused: M = wq^T@wk (16384) + b2 (128)
__device__ float g_qk  [N_CNT * D_DIM];
__device__ float g_mix [N_CNT * D_DIM];
__device__ float g_t1  [N_CNT * D_DIM];
__device__ float g_t2  [N_CNT * D_DIM];
__device__ __half g_egoh[N_CNT * D_DIM];
__device__ __half g_sim[(size_t)N_CNT * N_CNT];   // 512 MB scratch
__device__ __half g_smax[(size_t)N_CNT * 128];    // per-row strip maxima (4 MB)
__device__ int   g_cand[N_CNT * NCAND];
__device__ int   g_topk[N_CNT * K_TOP];
__device__ unsigned g_cmax[2 * D_DIM];
__device__ float    g_csum[2 * D_DIM];
__device__ unsigned g_skey[2];       // [0]=max||ego||^2, [1]=max||ego-mu||^2
__device__ float    g_scale[1];
__device__ float    g_mu[D_DIM];
__device__ float    g_cvec[N_CNT];   // c_i = <ego_i, mu>
// CSR scratch
__device__ int   g_rowstart[N_CNT + 1];
__device__ int   g_cursor[N_CNT];
__device__ int   g_ecol[E_CNT];
__device__ float g_eval[E_CNT];

// ---------------- helpers ----------------
__device__ __forceinline__ unsigned f2key(float f) {
    int i = __float_as_int(f);
    return (unsigned)i ^ (unsigned)((i >> 31) | 0x80000000);
}
__device__ __forceinline__ float key2f(unsigned k) {
    int i;
    if (k & 0x80000000u) i = (int)(k ^ 0x80000000u);
    else                 i = (int)(~k);
    return __int_as_float(i);
}
__device__ __forceinline__ unsigned smem_u32(const void* p) {
    return (unsigned)__cvta_generic_to_shared(p);
}
__device__ __forceinline__ unsigned h2u(__half2 v) {
    return *reinterpret_cast<unsigned*>(&v);
}
__device__ __forceinline__ void ldmat4(unsigned& r0, unsigned& r1, unsigned& r2, unsigned& r3, unsigned a) {
    asm volatile("ldmatrix.sync.aligned.m8n8.x4.shared.b16 {%0,%1,%2,%3}, [%4];"
                 : "=r"(r0), "=r"(r1), "=r"(r2), "=r"(r3) : "r"(a));
}
__device__ __forceinline__ void mma16816(float* c, unsigned a0, unsigned a1, unsigned a2, unsigned a3,
                                         unsigned b0, unsigned b1) {
    asm volatile("mma.sync.aligned.m16n8k16.row.col.f32.f16.f16.f32 "
                 "{%0,%1,%2,%3}, {%4,%5,%6,%7}, {%8,%9}, {%0,%1,%2,%3};"
                 : "+f"(c[0]), "+f"(c[1]), "+f"(c[2]), "+f"(c[3])
                 : "r"(a0), "r"(a1), "r"(a2), "r"(a3), "r"(b0), "r"(b1));
}
__device__ __forceinline__ void cp16(unsigned dst, const void* src) {
    asm volatile("cp.async.cg.shared.global [%0], [%1], 16;" :: "r"(dst), "l"(src));
}
#define CP_COMMIT() asm volatile("cp.async.commit_group;" ::: "memory")
#define CP_WAIT0()  asm volatile("cp.async.wait_group 0;" ::: "memory")

// ---------------- trivial kernels ----------------
__global__ void zero_int_kernel(int* __restrict__ p, int n) {
    int i = blockIdx.x * blockDim.x + threadIdx.x;
    if (i < n) p[i] = 0;
}
__global__ void mean3_kernel(const float* __restrict__ a, const float* __restrict__ b,
                             const float* __restrict__ c, float* __restrict__ out, int n) {
    int i = blockIdx.x * blockDim.x + threadIdx.x;
    if (i < n) out[i] = (a[i] + b[i] + c[i]) * (1.0f / 3.0f);
}
__global__ void cvt_h_kernel(const float* __restrict__ x, __half* __restrict__ y) {
    int i = blockIdx.x * blockDim.x + threadIdx.x;
    float4 v = reinterpret_cast<const float4*>(x)[i];
    reinterpret_cast<__half2*>(y)[2 * i + 0] = __floats2half2_rn(v.x, v.y);
    reinterpret_cast<__half2*>(y)[2 * i + 1] = __floats2half2_rn(v.z, v.w);
}
// column mean accumulate
__global__ void __launch_bounds__(128) colmean_kernel(const float* __restrict__ ego,
                                                      float* __restrict__ mu) {
    int d = threadIdx.x;
    int r0 = blockIdx.x * 128;
    float s = 0.0f;
    for (int r = r0; r < r0 + 128; r++) s += ego[(size_t)r * D_DIM + d];
    atomicAdd(&mu[d], s);
}
__global__ void mufin_kernel(float* __restrict__ mu) {
    mu[threadIdx.x] *= (1.0f / N_CNT);
}
// fused row stats: c_i = <ego_i, mu>; skey[0] = max||ego||^2; skey[1] = max||ego - mu||^2
__global__ void __launch_bounds__(256) rowdot_kernel(const float* __restrict__ ego,
                                                     const float* __restrict__ mu,
                                                     float* __restrict__ c,
                                                     unsigned* __restrict__ keys) {
    int r = (blockIdx.x * 256 + threadIdx.x) >> 5;
    int lane = threadIdx.x & 31;
    float4 v = *reinterpret_cast<const float4*>(&ego[(size_t)r * D_DIM + lane * 4]);
    float4 m = *reinterpret_cast<const float4*>(&mu[lane * 4]);
    float nrm = v.x * v.x + v.y * v.y + v.z * v.z + v.w * v.w;
    float dot = v.x * m.x + v.y * m.y + v.z * m.z + v.w * m.w;
    float dx = v.x - m.x, dy = v.y - m.y, dz = v.z - m.z, dw = v.w - m.w;
    float dev = dx * dx + dy * dy + dz * dz + dw * dw;
#pragma unroll
    for (int off = 16; off > 0; off >>= 1) {
        nrm += __shfl_xor_sync(0xffffffffu, nrm, off);
        dot += __shfl_xor_sync(0xffffffffu, dot, off);
        dev += __shfl_xor_sync(0xffffffffu, dev, off);
    }
    if (lane == 0) {
        c[r] = dot;
        atomicMax(&keys[0], f2key(nrm));
        atomicMax(&keys[1], f2key(dev));
    }
}
__global__ void scale2_kernel(const unsigned* __restrict__ skey, float* __restrict__ scale) {
    float a = sqrtf(fmaxf(key2f(skey[0]), 1e-30f));
    float b = sqrtf(fmaxf(key2f(skey[1]), 1e-30f));
    *scale = 16384.0f / fmaxf(a * b, 1e-30f);
}
// M[e][c] = sum_d wq[d][e]*wk[d][c] ; b2[c] = sum_d bq[d]*wk[d][c]
__global__ void wqk_kernel(const float* __restrict__ wq, const float* __restrict__ wk,
                           const float* __restrict__ bq, float* __restrict__ M) {
    int e = blockIdx.x, c = threadIdx.x;
    float s = 0.0f;
    for (int d = 0; d < D_DIM; d++) s += wq[d * D_DIM + e] * wk[d * D_DIM + c];
    M[e * D_DIM + c] = s;
    if (e == 0) {
        float b = 0.0f;
        for (int d = 0; d < D_DIM; d++) b += bq[d] * wk[d * D_DIM + c];
        M[D_DIM * D_DIM + c] = b;
    }
}

// ---------------- CSR build ----------------
__global__ void hist_kernel(const int* __restrict__ rows, int* __restrict__ cnt) {
    int e = blockIdx.x * blockDim.x + threadIdx.x;
    if (e < E_CNT) atomicAdd(&cnt[rows[e]], 1);
}
__global__ void __launch_bounds__(512) scan_kernel(int* __restrict__ cnt,
                                                   int* __restrict__ rowstart,
                                                   int* __restrict__ cursor) {
    __shared__ int ssum[512];
    int t = threadIdx.x;
    int base = t * 32;
    int local[32];
    int s = 0;
#pragma unroll
    for (int j = 0; j < 32; j++) { local[j] = cnt[base + j]; s += local[j]; }
    ssum[t] = s;
    __syncthreads();
    for (int off = 1; off < 512; off <<= 1) {
        int v = (t >= off) ? ssum[t - off] : 0;
        __syncthreads();
        ssum[t] += v;
        __syncthreads();
    }
    int run = (t > 0) ? ssum[t - 1] : 0;
#pragma unroll
    for (int j = 0; j < 32; j++) {
        rowstart[base + j] = run;
        cursor[base + j] = run;
        run += local[j];
    }
    if (t == 511) rowstart[N_CNT] = run;
}
__global__ void scatter_kernel(const int* __restrict__ rows, const int* __restrict__ cols,
                               const float* __restrict__ vals, int* __restrict__ cursor,
                               int* __restrict__ ecol, float* __restrict__ eval) {
    int e = blockIdx.x * blockDim.x + threadIdx.x;
    if (e >= E_CNT) return;
    int pos = atomicAdd(&cursor[rows[e]], 1);
    ecol[pos] = cols[e];
    eval[pos] = vals[e];
}
// warp per row, no atomics (R10 form)
__global__ void __launch_bounds__(256) spmm_csr_kernel(
    const float* __restrict__ xu, const float* __restrict__ xi,
    const int* __restrict__ rowstart, const int* __restrict__ ecol,
    const float* __restrict__ eval, float* __restrict__ y)
{
    int r = (blockIdx.x * 256 + threadIdx.x) >> 5;
    int lane = threadIdx.x & 31;
    if (r >= N_CNT) return;
    int s = rowstart[r], e = rowstart[r + 1];
    float4 acc = make_float4(0.f, 0.f, 0.f, 0.f);
#pragma unroll 2
    for (int i = s; i < e; i++) {
        int c = __ldg(&ecol[i]);
        float v = __ldg(&eval[i]);
        const float* src = (c < U_CNT) ? (xu + (size_t)c * D_DIM)
                                       : (xi + (size_t)(c - U_CNT) * D_DIM);
        float4 x = *reinterpret_cast<const float4*>(src + lane * 4);
        acc.x += v * x.x; acc.y += v * x.y; acc.z += v * x.z; acc.w += v * x.w;
    }
    *reinterpret_cast<float4*>(y + (size_t)r * D_DIM + lane * 4) = acc;
}

// ---------------- phase A: symmetric sim GEMM (fp16 HMMA, offset removed, strip-max emit) ----------------
#define TSH_OFF  67584
#define TSH_STR  136   // halfs; 272B row = 16B-aligned
#define GEMM_SMEM 102400

__global__ void __launch_bounds__(256, 2) simgemm_kernel(
    const __half* __restrict__ egh, __half* __restrict__ sim,
    __half* __restrict__ smax,
    const float* __restrict__ scalep, const float* __restrict__ cvec)
{
    const int bx = blockIdx.x, by = blockIdx.y;
    if (bx < by) return;          // upper triangle only
    extern __shared__ char sh[];
    const int tid = threadIdx.x;
    const int lane = tid & 31;
    const int wid = tid >> 5;
    const int wm = wid >> 1, wn = wid & 1;
    const int rowbase = by * 128;
    const int colbase = bx * 128;
    float* simf = (float*)sh;
    __half* tsh = (__half*)(sh + TSH_OFF);
    const unsigned aBase = smem_u32(sh);
    const unsigned bBase = aBase + 34816;
    const float scl = *scalep;

#pragma unroll
    for (int i = 0; i < 8; i++) {
        int ch = tid + i * 256;
        int row = ch >> 4, off = ch & 15;
        cp16(aBase + row * 272 + off * 16, egh + (size_t)(rowbase + row) * D_DIM + off * 8);
        cp16(bBase + row * 272 + off * 16, egh + (size_t)(colbase + row) * D_DIM + off * 8);
    }
    CP_COMMIT();
    CP_WAIT0();
    __syncthreads();

    float acc[2][8][4];
#pragma unroll
    for (int mt = 0; mt < 2; mt++)
#pragma unroll
        for (int nt = 0; nt < 8; nt++)
#pragma unroll
            for (int q = 0; q < 4; q++) acc[mt][nt][q] = 0.0f;

#pragma unroll
    for (int ks = 0; ks < 8; ks++) {
        unsigned a0[4], a1[4];
        ldmat4(a0[0], a0[1], a0[2], a0[3],
               aBase + (wm * 32 + 0 + (lane & 15)) * 272 + ks * 32 + (lane >> 4) * 16);
        ldmat4(a1[0], a1[1], a1[2], a1[3],
               aBase + (wm * 32 + 16 + (lane & 15)) * 272 + ks * 32 + (lane >> 4) * 16);
#pragma unroll
        for (int np = 0; np < 4; np++) {
            unsigned b0, b1, b2, b3;
            ldmat4(b0, b1, b2, b3,
                   bBase + (wn * 64 + np * 16 + ((lane >> 4) & 1) * 8 + (lane & 7)) * 272
                        + ks * 32 + ((lane >> 3) & 1) * 16);
            mma16816(acc[0][2 * np + 0], a0[0], a0[1], a0[2], a0[3], b0, b1);
            mma16816(acc[1][2 * np + 0], a1[0], a1[1], a1[2], a1[3], b0, b1);
            mma16816(acc[0][2 * np + 1], a0[0], a0[1], a0[2], a0[3], b2, b3);
            mma16816(acc[1][2 * np + 1], a1[0], a1[1], a1[2], a1[3], b2, b3);
        }
    }
#pragma unroll
    for (int mt = 0; mt < 2; mt++)
#pragma unroll
        for (int nt = 0; nt < 8; nt++)
#pragma unroll
            for (int q = 0; q < 4; q++) acc[mt][nt][q] *= scl;

    __syncthreads();   // operands dead; simf aliases them

    {
        int g = lane >> 2, t4 = lane & 3;
#pragma unroll
        for (int mt = 0; mt < 2; mt++)
#pragma unroll
            for (int nt = 0; nt < 8; nt++) {
                int r0 = wm * 32 + mt * 16 + g;
                int c  = wn * 64 + nt * 8 + 2 * t4;
                *reinterpret_cast<float2*>(&simf[r0 * 132 + c]) =
                    make_float2(acc[mt][nt][0], acc[mt][nt][1]);
                *reinterpret_cast<float2*>(&simf[(r0 + 8) * 132 + c]) =
                    make_float2(acc[mt][nt][2], acc[mt][nt][3]);
            }
    }
    __syncthreads();

    // normal store (fp16, coalesced), offset removed; emit per-row strip max
#pragma unroll
    for (int k = 0; k < 8; k++) {
        int i = tid + k * 256;
        int row = i >> 4, seg = i & 15;
        float csub = __ldg(&cvec[rowbase + row]) * scl;
        const float* p = &simf[row * 132 + seg * 8];
        float4 f0 = *reinterpret_cast<const float4*>(p);
        float4 f1 = *reinterpret_cast<const float4*>(p + 4);
        float a0 = f0.x - csub, a1 = f0.y - csub, a2 = f0.z - csub, a3 = f0.w - csub;
        float a4 = f1.x - csub, a5 = f1.y - csub, a6 = f1.z - csub, a7 = f1.w - csub;
        uint4 o;
        o.x = h2u(__floats2half2_rn(a0, a1));
        o.y = h2u(__floats2half2_rn(a2, a3));
        o.z = h2u(__floats2half2_rn(a4, a5));
        o.w = h2u(__floats2half2_rn(a6, a7));
        *reinterpret_cast<uint4*>(&sim[(size_t)(rowbase + row) * N_CNT + colbase + seg * 8]) = o;
        float m8 = fmaxf(fmaxf(fmaxf(a0, a1), fmaxf(a2, a3)),
                         fmaxf(fmaxf(a4, a5), fmaxf(a6, a7)));
#pragma unroll
        for (int off = 8; off > 0; off >>= 1)
            m8 = fmaxf(m8, __shfl_xor_sync(0xffffffffu, m8, off));
        if ((lane & 15) == 0)
            smax[(size_t)(rowbase + row) * 128 + bx] = __float2half(m8);
    }

    if (bx != by) {
        // transposed restage: mirror row is colbase+ci -> subtract c_j*scl
#pragma unroll
        for (int i = tid; i < 2048; i += 256) {
            int ci = i & 127, seg = i >> 7;
            float csub = __ldg(&cvec[colbase + ci]) * scl;
            float v[8];
#pragma unroll
            for (int k = 0; k < 8; k++) v[k] = simf[(seg * 8 + k) * 132 + ci] - csub;
            uint4 o;
            o.x = h2u(__floats2half2_rn(v[0], v[1]));
            o.y = h2u(__floats2half2_rn(v[2], v[3]));
            o.z = h2u(__floats2half2_rn(v[4], v[5]));
            o.w = h2u(__floats2half2_rn(v[6], v[7]));
            *reinterpret_cast<uint4*>(&tsh[ci * TSH_STR + seg * 8]) = o;
        }
        __syncthreads();
        // coalesced mirror store + strip-max emit
#pragma unroll
        for (int k = 0; k < 8; k++) {
            int i = tid + k * 256;
            int ci = i >> 4, seg = i & 15;
            uint4 o = *reinterpret_cast<const uint4*>(&tsh[ci * TSH_STR + seg * 8]);
            *reinterpret_cast<uint4*>(&sim[(size_t)(colbase + ci) * N_CNT + rowbase + seg * 8]) = o;
            float2 q0 = __half22float2(*reinterpret_cast<__half2*>(&o.x));
            float2 q1 = __half22float2(*reinterpret_cast<__half2*>(&o.y));
            float2 q2 = __half22float2(*reinterpret_cast<__half2*>(&o.z));
            float2 q3 = __half22float2(*reinterpret_cast<__half2*>(&o.w));
            float m8 = fmaxf(fmaxf(fmaxf(q0.x, q0.y), fmaxf(q1.x, q1.y)),
                             fmaxf(fmaxf(q2.x, q2.y), fmaxf(q3.x, q3.y)));
#pragma unroll
            for (int off = 8; off > 0; off >>= 1)
                m8 = fmaxf(m8, __shfl_xor_sync(0xffffffffu, m8, off));
            if ((lane & 15) == 0)
                smax[(size_t)(colbase + ci) * 128 + by] = __float2half(m8);
        }
    }
}

// ---------------- sorted top-64 insert (warp-distributed, descending) ----------------
__device__ __forceinline__ float ins64(float& s0, int& i0, float& s1, int& i1,
                                       float v, int ix, int lane) {
    unsigned b0 = __ballot_sync(0xffffffffu, s0 > v);
    unsigned b1 = __ballot_sync(0xffffffffu, s1 > v);
    int p = __popc(b0) + __popc(b1);
    float s0p = __shfl_up_sync(0xffffffffu, s0, 1);
    int   i0p = __shfl_up_sync(0xffffffffu, i0, 1);
    float s1p = __shfl_up_sync(0xffffffffu, s1, 1);
    int   i1p = __shfl_up_sync(0xffffffffu, i1, 1);
    float s31 = __shfl_sync(0xffffffffu, s0, 31);
    int   i31 = __shfl_sync(0xffffffffu, i0, 31);
    if (lane == 0) { s1p = s31; i1p = i31; }
    if (lane > p)       { s0 = s0p; i0 = i0p; }
    else if (lane == p) { s0 = v;   i0 = ix;  }
    int r1 = 32 + lane;
    if (r1 > p)         { s1 = s1p; i1 = i1p; }
    else if (r1 == p)   { s1 = v;   i1 = ix;  }
    return __shfl_sync(0xffffffffu, s1, 31);
}

// ---------------- phase B: strip-max-guided top-64 scan (exact skip) ----------------
__global__ void __launch_bounds__(256) select_kernel(
    const __half* __restrict__ sim, const __half* __restrict__ smax,
    int* __restrict__ cand)
{
    int r = (blockIdx.x * 256 + threadIdx.x) >> 5;
    int lane = threadIdx.x & 31;
    if (r >= N_CNT) return;

    const __half* smrow = smax + (size_t)r * 128;
    float sm[4];
#pragma unroll
    for (int j = 0; j < 4; j++) sm[j] = __half2float(__ldg(&smrow[lane * 4 + j]));

    const __half* rowp = sim + (size_t)r * N_CNT;
    float s0 = -INFINITY, s1 = -INFINITY;
    int i0 = 0, i1 = 0;
    float thr = -INFINITY;

    for (int it = 0; it < 128; it++) {
        // warp argmax over remaining strip maxima
        float lm = sm[0]; int lj = 0;
#pragma unroll
        for (int j = 1; j < 4; j++) if (sm[j] > lm) { lm = sm[j]; lj = j; }
        float bm = lm; int bl = lane; int bj = lj;
#pragma unroll
        for (int off = 16; off > 0; off >>= 1) {
            float om = __shfl_xor_sync(0xffffffffu, bm, off);
            int   ol = __shfl_xor_sync(0xffffffffu, bl, off);
            int   oj = __shfl_xor_sync(0xffffffffu, bj, off);
            if (om > bm || (om == bm && ol < bl)) { bm = om; bl = ol; bj = oj; }
        }
        if (!(bm > thr)) break;        // no remaining strip can beat rank-63
        if (lane == bl) sm[bj] = -INFINITY;
        int strip = bl * 4 + bj;

        uint2 raw = __ldg(reinterpret_cast<const uint2*>(rowp + strip * 128) + lane);
        float2 p0 = __half22float2(*reinterpret_cast<__half2*>(&raw.x));
        float2 p1 = __half22float2(*reinterpret_cast<__half2*>(&raw.y));
        float mx = fmaxf(fmaxf(p0.x, p0.y), fmaxf(p1.x, p1.y));
        unsigned m = __ballot_sync(0xffffffffu, mx > thr);
        while (m) {
            int src = __ffs(m) - 1;
            m &= m - 1;
            float w0 = __shfl_sync(0xffffffffu, p0.x, src);
            float w1 = __shfl_sync(0xffffffffu, p0.y, src);
            float w2 = __shfl_sync(0xffffffffu, p1.x, src);
            float w3 = __shfl_sync(0xffffffffu, p1.y, src);
            int cb = strip * 128 + src * 4;
            if (w0 > thr) thr = ins64(s0, i0, s1, i1, w0, cb + 0, lane);
            if (w1 > thr) thr = ins64(s0, i0, s1, i1, w1, cb + 1, lane);
            if (w2 > thr) thr = ins64(s0, i0, s1, i1, w2, cb + 2, lane);
            if (w3 > thr) thr = ins64(s0, i0, s1, i1, w3, cb + 3, lane);
        }
    }
    cand[r * NCAND + lane] = i0;
    cand[r * NCAND + 32 + lane] = i1;
}

// ---------------- fp32 rescore of 64 candidates -> exact top-32 set ----------------
__global__ void __launch_bounds__(256) rescore_kernel(
    const float* __restrict__ ego, const int* __restrict__ cand, int* __restrict__ topk)
{
    __shared__ float rsh[8 * 128];
    __shared__ int   csh[8 * NCAND];
    int tid = threadIdx.x, lane = tid & 31, w = tid >> 5;
    int Rbase = blockIdx.x * 8;
    reinterpret_cast<float4*>(rsh)[tid] =
        reinterpret_cast<const float4*>(ego + (size_t)Rbase * D_DIM)[tid];
    int R = Rbase + w;
    csh[w * NCAND + lane]      = cand[R * NCAND + lane];
    csh[w * NCAND + 32 + lane] = cand[R * NCAND + 32 + lane];
    __syncthreads();

    float4 a = reinterpret_cast<const float4*>(rsh + w * 128)[lane];
    float val0 = -INFINITY, val1 = -INFINITY;
    int   id0 = 0, id1 = 0;
#pragma unroll
    for (int k = 0; k < NCAND; k++) {
        int ck = csh[w * NCAND + k];
        float4 b = reinterpret_cast<const float4*>(ego)[(size_t)ck * 32 + lane];
        float p = a.x * b.x + a.y * b.y + a.z * b.z + a.w * b.w;
#pragma unroll
        for (int off = 16; off > 0; off >>= 1) p += __shfl_xor_sync(0xffffffffu, p, off);
        if (k < 32) { if (lane == k)      { val0 = p; id0 = ck; } }
        else        { if (lane == k - 32) { val1 = p; id1 = ck; } }
    }
    for (int it = 0; it < K_TOP; it++) {
        float bm = fmaxf(val0, val1); int bl = lane;
#pragma unroll
        for (int off = 16; off > 0; off >>= 1) {
            float om = __shfl_xor_sync(0xffffffffu, bm, off);
            int   ol = __shfl_xor_sync(0xffffffffu, bl, off);
            if (om > bm || (om == bm && ol < bl)) { bm = om; bl = ol; }
        }
        if (lane == bl) {
            if (val1 > val0) { topk[R * K_TOP + it] = id1; val1 = -INFINITY; }
            else             { topk[R * K_TOP + it] = id0; val0 = -INFINITY; }
        }
    }
}

// ---------------- small fp32 GEMM ----------------
__global__ void __launch_bounds__(256, 2) gemm_kernel(
    const float* __restrict__ A, const float* __restrict__ W,
    const float* __restrict__ bias, const float* __restrict__ aux,
    float* __restrict__ out, int trans, int epi)
{
    extern __shared__ float shf[];
    float* Wsh = shf;
    float* Ash = shf + 128 * PAD;
    const int tid = threadIdx.x;
    const int lane = tid & 31;
    const int wid = tid >> 5;
    const int rowbase = blockIdx.x * 32;

    if (!trans) {
        for (int i = tid; i < 128 * 32; i += 256) {
            int c = i >> 5, e4 = i & 31;
            float4 v = *reinterpret_cast<const float4*>(&W[c * D_DIM + e4 * 4]);
            *reinterpret_cast<float4*>(&Wsh[c * PAD + e4 * 4]) = v;
        }
    } else {
        for (int i = tid; i < 128 * 128; i += 256) {
            int e = i >> 7, c = i & 127;
            Wsh[c * PAD + e] = W[i];
        }
    }
    for (int i = tid; i < 32 * 32; i += 256) {
        int r = i >> 5, d4 = i & 31;
        float4 v = *reinterpret_cast<const float4*>(&A[(size_t)(rowbase + r) * D_DIM + d4 * 4]);
        *reinterpret_cast<float4*>(&Ash[r * PAD + d4 * 4]) = v;
    }
    __syncthreads();

    float acc[4][4];
#pragma unroll
    for (int j = 0; j < 4; j++)
#pragma unroll
        for (int k = 0; k < 4; k++) acc[j][k] = 0.0f;

    const float* abase = Ash + (wid * 4) * PAD;
    const float* wbase = Wsh + lane * PAD;
#pragma unroll 8
    for (int d = 0; d < D_DIM; d += 4) {
        float4 a0 = *reinterpret_cast<const float4*>(abase + 0 * PAD + d);
        float4 a1 = *reinterpret_cast<const float4*>(abase + 1 * PAD + d);
        float4 a2 = *reinterpret_cast<const float4*>(abase + 2 * PAD + d);
        float4 a3 = *reinterpret_cast<const float4*>(abase + 3 * PAD + d);
        float4 w0 = *reinterpret_cast<const float4*>(wbase + 0 * PAD + d);
        float4 w1 = *reinterpret_cast<const float4*>(wbase + 32 * PAD + d);
        float4 w2 = *reinterpret_cast<const float4*>(wbase + 64 * PAD + d);
        float4 w3 = *reinterpret_cast<const float4*>(wbase + 96 * PAD + d);
#define DO4(j, av) \
        acc[j][0] += av.x*w0.x + av.y*w0.y + av.z*w0.z + av.w*w0.w; \
        acc[j][1] += av.x*w1.x + av.y*w1.y + av.z*w1.z + av.w*w1.w; \
        acc[j][2] += av.x*w2.x + av.y*w2.y + av.z*w2.z + av.w*w2.w; \
        acc[j][3] += av.x*w3.x + av.y*w3.y + av.z*w3.z + av.w*w3.w;
        DO4(0, a0) DO4(1, a1) DO4(2, a2) DO4(3, a3)
#undef DO4
    }

#pragma unroll
    for (int j = 0; j < 4; j++) {
        int n = rowbase + wid * 4 + j;
#pragma unroll
        for (int k = 0; k < 4; k++) {
            int c = lane + 32 * k;
            float v = acc[j][k];
            if (bias) v += bias[c];
            if (epi == 1) v = tanhf(v);
            else if (epi == 2) v += 0.1f * aux[(size_t)n * D_DIM + c];
            out[(size_t)n * D_DIM + c] = v;
        }
    }
}

// ---------------- attention over top-32 ----------------
__global__ void __launch_bounds__(256) attn_kernel(
    const float* __restrict__ ego, const float* __restrict__ qk,
    const int* __restrict__ topk, float* __restrict__ mix)
{
    int n = (blockIdx.x * 256 + threadIdx.x) >> 5;
    int lane = threadIdx.x & 31;
    if (n >= N_CNT) return;

    float4 qv = *reinterpret_cast<const float4*>(&qk[(size_t)n * D_DIM + lane * 4]);
    int myidx = topk[(size_t)n * K_TOP + lane];
    float myscore = 0.0f;
#pragma unroll 4
    for (int k = 0; k < K_TOP; k++) {
        int id = __shfl_sync(0xffffffffu, myidx, k);
        float4 e = *reinterpret_cast<const float4*>(&ego[(size_t)id * D_DIM + lane * 4]);
        float p = qv.x * e.x + qv.y * e.y + qv.z * e.z + qv.w * e.w;
#pragma unroll
        for (int off = 16; off > 0; off >>= 1) p += __shfl_xor_sync(0xffffffffu, p, off);
        if (lane == k) myscore = p * 0.08838834764831845f;
    }
    float m = myscore;
#pragma unroll
    for (int off = 16; off > 0; off >>= 1) m = fmaxf(m, __shfl_xor_sync(0xffffffffu, m, off));
    float ex = expf(myscore - m);
    float z = ex;
#pragma unroll
    for (int off = 16; off > 0; off >>= 1) z += __shfl_xor_sync(0xffffffffu, z, off);
    float a = ex / z;

    float4 accv = make_float4(0.f, 0.f, 0.f, 0.f);
#pragma unroll 4
    for (int k = 0; k < K_TOP; k++) {
        float ak = __shfl_sync(0xffffffffu, a, k);
        int id = __shfl_sync(0xffffffffu, myidx, k);
        float4 e = *reinterpret_cast<const float4*>(&ego[(size_t)id * D_DIM + lane * 4]);
        accv.x += ak * e.x; accv.y += ak * e.y; accv.z += ak * e.z; accv.w += ak * e.w;
    }
    *reinterpret_cast<float4*>(&mix[(size_t)n * D_DIM + lane * 4]) = accv;
}

// ---------------- fusion column softmax ----------------
__global__ void colinit_kernel(unsigned* cmax, float* csum) {
    int i = threadIdx.x;
    if (i < 2 * D_DIM) { cmax[i] = f2key(-1e30f); csum[i] = 0.0f; }
}
__global__ void __launch_bounds__(128) colmax_kernel(const float* __restrict__ t, unsigned* __restrict__ cmax) {
    int d = threadIdx.x;
    int r0 = blockIdx.x * 128;
    float m = -1e30f;
    for (int r = r0; r < r0 + 128; r++) m = fmaxf(m, t[(size_t)r * D_DIM + d]);
    atomicMax(&cmax[d], f2key(m));
}
__global__ void __launch_bounds__(128) colsum_kernel(const float* __restrict__ t,
                                                     const unsigned* __restrict__ cmax,
                                                     float* __restrict__ csum) {
    int d = threadIdx.x;
    int r0 = blockIdx.x * 128;
    float mx = key2f(cmax[d]);
    float s = 0.0f;
    for (int r = r0; r < r0 + 128; r++) s += expf(t[(size_t)r * D_DIM + d] - mx);
    atomicAdd(&csum[d], s);
}
__global__ void fusion_kernel(const float* __restrict__ t1, const float* __restrict__ t2,
                              const unsigned* __restrict__ cmax, const float* __restrict__ csum,
                              const float* __restrict__ all, const float* __restrict__ atten,
                              float* __restrict__ out, int n) {
    int i = blockIdx.x * blockDim.x + threadIdx.x;
    if (i >= n) return;
    int d = i & (D_DIM - 1);
    float w1 = expf(t1[i] - key2f(cmax[d]))         / csum[d];
    float w2 = expf(t2[i] - key2f(cmax[D_DIM + d])) / csum[D_DIM + d];
    out[i] = w1 * all[i] + w2 * atten[i];
}

// ---------------- launch ----------------
extern "C" void kernel_launch(void* const* d_in, const int* in_sizes, int n_in,
                              void* d_out, int out_size) {
    const float* user = (const float*)d_in[0];
    const float* item = (const float*)d_in[1];
    const int*   rows = (const int*)d_in[2];
    const int*   cols = (const int*)d_in[3];
    const float* vals = (const float*)d_in[4];
    const float* wq   = (const float*)d_in[5];
    const float* bq   = (const float*)d_in[6];
    const float* wk   = (const float*)d_in[7];
    const float* wv   = (const float*)d_in[9];
    const float* bv   = (const float*)d_in[10];
    const float* fw   = (const float*)d_in[11];
    const float* fb   = (const float*)d_in[12];

    const int ND = N_CNT * D_DIM;
    const int SMEM = (128 * PAD + 32 * PAD) * 4;
    cudaFuncSetAttribute(gemm_kernel, cudaFuncAttributeMaxDynamicSharedMemorySize, SMEM);
    cudaFuncSetAttribute(simgemm_kernel, cudaFuncAttributeMaxDynamicSharedMemorySize, GEMM_SMEM);

    float *bufA, *bufB, *ego, *qbuf, *qkb, *mixb, *t1, *t2, *csum, *eval, *scalef, *muf, *cvec;
    __half *egoh, *simp, *smaxp;
    int *cand, *topk, *rowstart, *cursor, *ecol;
    unsigned *cmax, *skey;
    cudaGetSymbolAddress((void**)&bufA, g_bufA);
    cudaGetSymbolAddress((void**)&bufB, g_bufB);
    cudaGetSymbolAddress((void**)&ego,  g_ego);
    cudaGetSymbolAddress((void**)&qbuf, g_q);
    cudaGetSymbolAddress((void**)&qkb,  g_qk);
    cudaGetSymbolAddress((void**)&mixb, g_mix);
    cudaGetSymbolAddress((void**)&t1,   g_t1);
    cudaGetSymbolAddress((void**)&t2,   g_t2);
    cudaGetSymbolAddress((void**)&egoh, g_egoh);
    cudaGetSymbolAddress((void**)&simp, g_sim);
    cudaGetSymbolAddress((void**)&smaxp, g_smax);
    cudaGetSymbolAddress((void**)&cand, g_cand);
    cudaGetSymbolAddress((void**)&topk, g_topk);
    cudaGetSymbolAddress((void**)&cmax, g_cmax);
    cudaGetSymbolAddress((void**)&csum, g_csum);
    cudaGetSymbolAddress((void**)&skey, g_skey);
    cudaGetSymbolAddress((void**)&scalef, g_scale);
    cudaGetSymbolAddress((void**)&muf, g_mu);
    cudaGetSymbolAddress((void**)&cvec, g_cvec);
    cudaGetSymbolAddress((void**)&rowstart, g_rowstart);
    cudaGetSymbolAddress((void**)&cursor, g_cursor);
    cudaGetSymbolAddress((void**)&ecol, g_ecol);
    cudaGetSymbolAddress((void**)&eval, g_eval);

    float* outAll = (float*)d_out;
    float* outAtt = outAll + ND;
    float* outFus = outAll + 2 * ND;

    const int ZB = ND / 256;
    const int EB = E_CNT / 256;
    const int RB = (N_CNT * 32) / 256;

    // CSR build (atomic-free SpMM afterwards)
    zero_int_kernel<<<N_CNT / 256, 256>>>(cursor, N_CNT);
    hist_kernel<<<EB, 256>>>(rows, cursor);
    scan_kernel<<<1, 512>>>(cursor, rowstart, cursor);
    scatter_kernel<<<EB, 256>>>(rows, cols, vals, cursor, ecol, eval);

    // 3 SpMM layers
    spmm_csr_kernel<<<RB, 256>>>(user, item, rowstart, ecol, eval, bufA);
    spmm_csr_kernel<<<RB, 256>>>(bufA, bufA + U_CNT * D_DIM, rowstart, ecol, eval, bufB);
    spmm_csr_kernel<<<RB, 256>>>(bufB, bufB + U_CNT * D_DIM, rowstart, ecol, eval, ego);
    mean3_kernel<<<ZB, 256>>>(bufA, bufB, ego, outAll, ND);

    // row-offset stats
    zero_int_kernel<<<1, 32>>>((int*)skey, 2);
    zero_int_kernel<<<1, 128>>>((int*)muf, D_DIM);
    colmean_kernel<<<N_CNT / 128, 128>>>(ego, muf);
    mufin_kernel<<<1, 128>>>(muf);
    rowdot_kernel<<<RB, 256>>>(ego, muf, cvec, skey);
    scale2_kernel<<<1, 1>>>(skey, scalef);

    // symmetric offset-removed fp16 sim GEMM (+strip max) -> guided top-64 -> fp32 rescore
    cvt_h_kernel<<<ND / 4 / 256, 256>>>(ego, egoh);
    simgemm_kernel<<<dim3(N_CNT / 128, N_CNT / 128), 256, GEMM_SMEM>>>(egoh, simp, smaxp, scalef, cvec);
    select_kernel<<<RB, 256>>>(simp, smaxp, cand);
    rescore_kernel<<<N_CNT / 8, 256>>>(ego, cand, topk);

    // qk = ego @ (wq^T wk) + bq@wk   (folded weights)
    wqk_kernel<<<128, 128>>>(wq, wk, bq, qbuf);
    gemm_kernel<<<N_CNT / 32, 256, SMEM>>>(ego, qbuf, qbuf + D_DIM * D_DIM, nullptr, qkb, 1, 0);
    attn_kernel<<<RB, 256>>>(ego, qkb, topk, mixb);
    gemm_kernel<<<N_CNT / 32, 256, SMEM>>>(mixb, wv, bv, ego, outAtt, 0, 2);

    gemm_kernel<<<N_CNT / 32, 256, SMEM>>>(outAll, fw, fb, nullptr, t1, 0, 1);
    gemm_kernel<<<N_CNT / 32, 256, SMEM>>>(outAtt, fw, fb, nullptr, t2, 0, 1);
    colinit_kernel<<<1, 256>>>(cmax, csum);
    colmax_kernel<<<N_CNT / 128, 128>>>(t1, cmax);
    colmax_kernel<<<N_CNT / 128, 128>>>(t2, cmax + D_DIM);
    colsum_kernel<<<N_CNT / 128, 128>>>(t1, cmax, csum);
    colsum_kernel<<<N_CNT / 128, 128>>>(t2, cmax + D_DIM, csum + D_DIM);
    fusion_kernel<<<ZB, 256>>>(t1, t2, cmax, csum, outAll, outAtt, outFus, ND);
}

// round 13
// speedup vs baseline: 1.0104x; 1.0104x over previous
#include <cuda_runtime.h>
#include <cuda_fp16.h>
#include <math.h>

#define U_CNT 8192
#define N_CNT 16384
#define D_DIM 128
#define E_CNT 524288
#define K_TOP 32
#define NCAND 64
#define PAD   132

// ---------------- scratch (device globals; no allocation) ----------------
__device__ float g_bufA[N_CNT * D_DIM];
__device__ float g_bufB[N_CNT * D_DIM];
__device__ float g_ego [N_CNT * D_DIM];
__device__ float g_q   [N_CNT * D_DIM];   // reused: M = wq^T@wk (16384) + b2 (128)
__device__ float g_qk  [N_CNT * D_DIM];
__device__ float g_mix [N_CNT * D_DIM];
__device__ float g_t1  [N_CNT * D_DIM];
__device__ float g_t2  [N_CNT * D_DIM];
__device__ __half g_egoh[N_CNT * D_DIM];
__device__ __half g_sim[(size_t)N_CNT * N_CNT];   // 512 MB scratch
__device__ __half g_smax[(size_t)N_CNT * 128];    // per-row strip maxima (4 MB)
__device__ int   g_cand[N_CNT * NCAND];
__device__ int   g_topk[N_CNT * K_TOP];
__device__ unsigned g_cmax[2 * D_DIM];
__device__ float    g_csum[2 * D_DIM];
__device__ unsigned g_skey[2];       // [0]=max||ego||^2, [1]=max||ego-mu||^2
__device__ float    g_scale[1];
__device__ float    g_mu[D_DIM];
__device__ float    g_cvec[N_CNT];   // c_i = <ego_i, mu>
// CSR scratch
__device__ int   g_rowstart[N_CNT + 1];
__device__ int   g_cursor[N_CNT];
__device__ int   g_ecol[E_CNT];
__device__ float g_eval[E_CNT];

// ---------------- helpers ----------------
__device__ __forceinline__ unsigned f2key(float f) {
    int i = __float_as_int(f);
    return (unsigned)i ^ (unsigned)((i >> 31) | 0x80000000);
}
__device__ __forceinline__ float key2f(unsigned k) {
    int i;
    if (k & 0x80000000u) i = (int)(k ^ 0x80000000u);
    else                 i = (int)(~k);
    return __int_as_float(i);
}
__device__ __forceinline__ unsigned smem_u32(const void* p) {
    return (unsigned)__cvta_generic_to_shared(p);
}
__device__ __forceinline__ unsigned h2u(__half2 v) {
    return *reinterpret_cast<unsigned*>(&v);
}
__device__ __forceinline__ void ldmat4(unsigned& r0, unsigned& r1, unsigned& r2, unsigned& r3, unsigned a) {
    asm volatile("ldmatrix.sync.aligned.m8n8.x4.shared.b16 {%0,%1,%2,%3}, [%4];"
                 : "=r"(r0), "=r"(r1), "=r"(r2), "=r"(r3) : "r"(a));
}
__device__ __forceinline__ void mma16816(float* c, unsigned a0, unsigned a1, unsigned a2, unsigned a3,
                                         unsigned b0, unsigned b1) {
    asm volatile("mma.sync.aligned.m16n8k16.row.col.f32.f16.f16.f32 "
                 "{%0,%1,%2,%3}, {%4,%5,%6,%7}, {%8,%9}, {%0,%1,%2,%3};"
                 : "+f"(c[0]), "+f"(c[1]), "+f"(c[2]), "+f"(c[3])
                 : "r"(a0), "r"(a1), "r"(a2), "r"(a3), "r"(b0), "r"(b1));
}
__device__ __forceinline__ void cp16(unsigned dst, const void* src) {
    asm volatile("cp.async.cg.shared.global [%0], [%1], 16;" :: "r"(dst), "l"(src));
}
#define CP_COMMIT() asm volatile("cp.async.commit_group;" ::: "memory")
#define CP_WAIT0()  asm volatile("cp.async.wait_group 0;" ::: "memory")

// ---------------- trivial kernels ----------------
__global__ void zero_int_kernel(int* __restrict__ p, int n) {
    int i = blockIdx.x * blockDim.x + threadIdx.x;
    if (i < n) p[i] = 0;
}
__global__ void mean3_kernel(const float* __restrict__ a, const float* __restrict__ b,
                             const float* __restrict__ c, float* __restrict__ out, int n) {
    int i = blockIdx.x * blockDim.x + threadIdx.x;
    if (i < n) out[i] = (a[i] + b[i] + c[i]) * (1.0f / 3.0f);
}
// column mean accumulate (scaled by 1/N inline)
__global__ void __launch_bounds__(128) colmean_kernel(const float* __restrict__ ego,
                                                      float* __restrict__ mu) {
    int d = threadIdx.x;
    int r0 = blockIdx.x * 128;
    float s = 0.0f;
    for (int r = r0; r < r0 + 128; r++) s += ego[(size_t)r * D_DIM + d];
    atomicAdd(&mu[d], s * (1.0f / N_CNT));
}
// fused row stats + fp16 convert:
// c_i = <ego_i, mu>; skey[0] = max||ego||^2; skey[1] = max||ego - mu||^2; egoh = half(ego)
__global__ void __launch_bounds__(256) rowdot_kernel(const float* __restrict__ ego,
                                                     const float* __restrict__ mu,
                                                     float* __restrict__ c,
                                                     unsigned* __restrict__ keys,
                                                     __half* __restrict__ egoh) {
    int r = (blockIdx.x * 256 + threadIdx.x) >> 5;
    int lane = threadIdx.x & 31;
    float4 v = *reinterpret_cast<const float4*>(&ego[(size_t)r * D_DIM + lane * 4]);
    float4 m = *reinterpret_cast<const float4*>(&mu[lane * 4]);
    uint2 oh;
    oh.x = h2u(__floats2half2_rn(v.x, v.y));
    oh.y = h2u(__floats2half2_rn(v.z, v.w));
    *reinterpret_cast<uint2*>(&egoh[(size_t)r * D_DIM + lane * 4]) = oh;
    float nrm = v.x * v.x + v.y * v.y + v.z * v.z + v.w * v.w;
    float dot = v.x * m.x + v.y * m.y + v.z * m.z + v.w * m.w;
    float dx = v.x - m.x, dy = v.y - m.y, dz = v.z - m.z, dw = v.w - m.w;
    float dev = dx * dx + dy * dy + dz * dz + dw * dw;
#pragma unroll
    for (int off = 16; off > 0; off >>= 1) {
        nrm += __shfl_xor_sync(0xffffffffu, nrm, off);
        dot += __shfl_xor_sync(0xffffffffu, dot, off);
        dev += __shfl_xor_sync(0xffffffffu, dev, off);
    }
    if (lane == 0) {
        c[r] = dot;
        atomicMax(&keys[0], f2key(nrm));
        atomicMax(&keys[1], f2key(dev));
    }
}
__global__ void scale2_kernel(const unsigned* __restrict__ skey, float* __restrict__ scale) {
    float a = sqrtf(fmaxf(key2f(skey[0]), 1e-30f));
    float b = sqrtf(fmaxf(key2f(skey[1]), 1e-30f));
    *scale = 16384.0f / fmaxf(a * b, 1e-30f);
}
// M[e][c] = sum_d wq[d][e]*wk[d][c] ; b2[c] = sum_d bq[d]*wk[d][c]
__global__ void wqk_kernel(const float* __restrict__ wq, const float* __restrict__ wk,
                           const float* __restrict__ bq, float* __restrict__ M) {
    int e = blockIdx.x, c = threadIdx.x;
    float s = 0.0f;
    for (int d = 0; d < D_DIM; d++) s += wq[d * D_DIM + e] * wk[d * D_DIM + c];
    M[e * D_DIM + c] = s;
    if (e == 0) {
        float b = 0.0f;
        for (int d = 0; d < D_DIM; d++) b += bq[d] * wk[d * D_DIM + c];
        M[D_DIM * D_DIM + c] = b;
    }
}

// ---------------- CSR build ----------------
__global__ void hist_kernel(const int* __restrict__ rows, int* __restrict__ cnt) {
    int e = blockIdx.x * blockDim.x + threadIdx.x;
    if (e < E_CNT) atomicAdd(&cnt[rows[e]], 1);
}
__global__ void __launch_bounds__(512) scan_kernel(int* __restrict__ cnt,
                                                   int* __restrict__ rowstart,
                                                   int* __restrict__ cursor) {
    __shared__ int ssum[512];
    int t = threadIdx.x;
    int base = t * 32;
    int local[32];
    int s = 0;
#pragma unroll
    for (int j = 0; j < 32; j++) { local[j] = cnt[base + j]; s += local[j]; }
    ssum[t] = s;
    __syncthreads();
    for (int off = 1; off < 512; off <<= 1) {
        int v = (t >= off) ? ssum[t - off] : 0;
        __syncthreads();
        ssum[t] += v;
        __syncthreads();
    }
    int run = (t > 0) ? ssum[t - 1] : 0;
#pragma unroll
    for (int j = 0; j < 32; j++) {
        rowstart[base + j] = run;
        cursor[base + j] = run;
        run += local[j];
    }
    if (t == 511) rowstart[N_CNT] = run;
}
__global__ void scatter_kernel(const int* __restrict__ rows, const int* __restrict__ cols,
                               const float* __restrict__ vals, int* __restrict__ cursor,
                               int* __restrict__ ecol, float* __restrict__ eval) {
    int e = blockIdx.x * blockDim.x + threadIdx.x;
    if (e >= E_CNT) return;
    int pos = atomicAdd(&cursor[rows[e]], 1);
    ecol[pos] = cols[e];
    eval[pos] = vals[e];
}
// warp per row, no atomics
__global__ void __launch_bounds__(256) spmm_csr_kernel(
    const float* __restrict__ xu, const float* __restrict__ xi,
    const int* __restrict__ rowstart, const int* __restrict__ ecol,
    const float* __restrict__ eval, float* __restrict__ y)
{
    int r = (blockIdx.x * 256 + threadIdx.x) >> 5;
    int lane = threadIdx.x & 31;
    if (r >= N_CNT) return;
    int s = rowstart[r], e = rowstart[r + 1];
    float4 acc = make_float4(0.f, 0.f, 0.f, 0.f);
#pragma unroll 2
    for (int i = s; i < e; i++) {
        int c = __ldg(&ecol[i]);
        float v = __ldg(&eval[i]);
        const float* src = (c < U_CNT) ? (xu + (size_t)c * D_DIM)
                                       : (xi + (size_t)(c - U_CNT) * D_DIM);
        float4 x = *reinterpret_cast<const float4*>(src + lane * 4);
        acc.x += v * x.x; acc.y += v * x.y; acc.z += v * x.z; acc.w += v * x.w;
    }
    *reinterpret_cast<float4*>(y + (size_t)r * D_DIM + lane * 4) = acc;
}

// ---------------- phase A: symmetric sim GEMM (fp16 HMMA, offset removed, strip-max emit) ----------------
#define TSH_OFF  67584
#define TSH_STR  136   // halfs; 272B row = 16B-aligned
#define GEMM_SMEM 102400

__global__ void __launch_bounds__(256, 2) simgemm_kernel(
    const __half* __restrict__ egh, __half* __restrict__ sim,
    __half* __restrict__ smax,
    const float* __restrict__ scalep, const float* __restrict__ cvec)
{
    const int bx = blockIdx.x, by = blockIdx.y;
    if (bx < by) return;          // upper triangle only
    extern __shared__ char sh[];
    const int tid = threadIdx.x;
    const int lane = tid & 31;
    const int wid = tid >> 5;
    const int wm = wid >> 1, wn = wid & 1;
    const int rowbase = by * 128;
    const int colbase = bx * 128;
    float* simf = (float*)sh;
    __half* tsh = (__half*)(sh + TSH_OFF);
    const unsigned aBase = smem_u32(sh);
    const unsigned bBase = aBase + 34816;
    const float scl = *scalep;

#pragma unroll
    for (int i = 0; i < 8; i++) {
        int ch = tid + i * 256;
        int row = ch >> 4, off = ch & 15;
        cp16(aBase + row * 272 + off * 16, egh + (size_t)(rowbase + row) * D_DIM + off * 8);
        cp16(bBase + row * 272 + off * 16, egh + (size_t)(colbase + row) * D_DIM + off * 8);
    }
    CP_COMMIT();
    CP_WAIT0();
    __syncthreads();

    float acc[2][8][4];
#pragma unroll
    for (int mt = 0; mt < 2; mt++)
#pragma unroll
        for (int nt = 0; nt < 8; nt++)
#pragma unroll
            for (int q = 0; q < 4; q++) acc[mt][nt][q] = 0.0f;

#pragma unroll
    for (int ks = 0; ks < 8; ks++) {
        unsigned a0[4], a1[4];
        ldmat4(a0[0], a0[1], a0[2], a0[3],
               aBase + (wm * 32 + 0 + (lane & 15)) * 272 + ks * 32 + (lane >> 4) * 16);
        ldmat4(a1[0], a1[1], a1[2], a1[3],
               aBase + (wm * 32 + 16 + (lane & 15)) * 272 + ks * 32 + (lane >> 4) * 16);
#pragma unroll
        for (int np = 0; np < 4; np++) {
            unsigned b0, b1, b2, b3;
            ldmat4(b0, b1, b2, b3,
                   bBase + (wn * 64 + np * 16 + ((lane >> 4) & 1) * 8 + (lane & 7)) * 272
                        + ks * 32 + ((lane >> 3) & 1) * 16);
            mma16816(acc[0][2 * np + 0], a0[0], a0[1], a0[2], a0[3], b0, b1);
            mma16816(acc[1][2 * np + 0], a1[0], a1[1], a1[2], a1[3], b0, b1);
            mma16816(acc[0][2 * np + 1], a0[0], a0[1], a0[2], a0[3], b2, b3);
            mma16816(acc[1][2 * np + 1], a1[0], a1[1], a1[2], a1[3], b2, b3);
        }
    }
#pragma unroll
    for (int mt = 0; mt < 2; mt++)
#pragma unroll
        for (int nt = 0; nt < 8; nt++)
#pragma unroll
            for (int q = 0; q < 4; q++) acc[mt][nt][q] *= scl;

    __syncthreads();   // operands dead; simf aliases them

    {
        int g = lane >> 2, t4 = lane & 3;
#pragma unroll
        for (int mt = 0; mt < 2; mt++)
#pragma unroll
            for (int nt = 0; nt < 8; nt++) {
                int r0 = wm * 32 + mt * 16 + g;
                int c  = wn * 64 + nt * 8 + 2 * t4;
                *reinterpret_cast<float2*>(&simf[r0 * 132 + c]) =
                    make_float2(acc[mt][nt][0], acc[mt][nt][1]);
                *reinterpret_cast<float2*>(&simf[(r0 + 8) * 132 + c]) =
                    make_float2(acc[mt][nt][2], acc[mt][nt][3]);
            }
    }
    __syncthreads();

    // normal store (fp16, coalesced), offset removed; emit per-row strip max
#pragma unroll
    for (int k = 0; k < 8; k++) {
        int i = tid + k * 256;
        int row = i >> 4, seg = i & 15;
        float csub = __ldg(&cvec[rowbase + row]) * scl;
        const float* p = &simf[row * 132 + seg * 8];
        float4 f0 = *reinterpret_cast<const float4*>(p);
        float4 f1 = *reinterpret_cast<const float4*>(p + 4);
        float a0 = f0.x - csub, a1 = f0.y - csub, a2 = f0.z - csub, a3 = f0.w - csub;
        float a4 = f1.x - csub, a5 = f1.y - csub, a6 = f1.z - csub, a7 = f1.w - csub;
        uint4 o;
        o.x = h2u(__floats2half2_rn(a0, a1));
        o.y = h2u(__floats2half2_rn(a2, a3));
        o.z = h2u(__floats2half2_rn(a4, a5));
        o.w = h2u(__floats2half2_rn(a6, a7));
        *reinterpret_cast<uint4*>(&sim[(size_t)(rowbase + row) * N_CNT + colbase + seg * 8]) = o;
        float m8 = fmaxf(fmaxf(fmaxf(a0, a1), fmaxf(a2, a3)),
                         fmaxf(fmaxf(a4, a5), fmaxf(a6, a7)));
#pragma unroll
        for (int off = 8; off > 0; off >>= 1)
            m8 = fmaxf(m8, __shfl_xor_sync(0xffffffffu, m8, off));
        if ((lane & 15) == 0)
            smax[(size_t)(rowbase + row) * 128 + bx] = __float2half(m8);
    }

    if (bx != by) {
        // transposed restage: mirror row is colbase+ci -> subtract c_j*scl
#pragma unroll
        for (int i = tid; i < 2048; i += 256) {
            int ci = i & 127, seg = i >> 7;
            float csub = __ldg(&cvec[colbase + ci]) * scl;
            float v[8];
#pragma unroll
            for (int k = 0; k < 8; k++) v[k] = simf[(seg * 8 + k) * 132 + ci] - csub;
            uint4 o;
            o.x = h2u(__floats2half2_rn(v[0], v[1]));
            o.y = h2u(__floats2half2_rn(v[2], v[3]));
            o.z = h2u(__floats2half2_rn(v[4], v[5]));
            o.w = h2u(__floats2half2_rn(v[6], v[7]));
            *reinterpret_cast<uint4*>(&tsh[ci * TSH_STR + seg * 8]) = o;
        }
        __syncthreads();
        // coalesced mirror store + strip-max emit
#pragma unroll
        for (int k = 0; k < 8; k++) {
            int i = tid + k * 256;
            int ci = i >> 4, seg = i & 15;
            uint4 o = *reinterpret_cast<const uint4*>(&tsh[ci * TSH_STR + seg * 8]);
            *reinterpret_cast<uint4*>(&sim[(size_t)(colbase + ci) * N_CNT + rowbase + seg * 8]) = o;
            float2 q0 = __half22float2(*reinterpret_cast<__half2*>(&o.x));
            float2 q1 = __half22float2(*reinterpret_cast<__half2*>(&o.y));
            float2 q2 = __half22float2(*reinterpret_cast<__half2*>(&o.z));
            float2 q3 = __half22float2(*reinterpret_cast<__half2*>(&o.w));
            float m8 = fmaxf(fmaxf(fmaxf(q0.x, q0.y), fmaxf(q1.x, q1.y)),
                             fmaxf(fmaxf(q2.x, q2.y), fmaxf(q3.x, q3.y)));
#pragma unroll
            for (int off = 8; off > 0; off >>= 1)
                m8 = fmaxf(m8, __shfl_xor_sync(0xffffffffu, m8, off));
            if ((lane & 15) == 0)
                smax[(size_t)(colbase + ci) * 128 + by] = __float2half(m8);
        }
    }
}

// ---------------- sorted top-64 insert (warp-distributed, descending) ----------------
__device__ __forceinline__ float ins64(float& s0, int& i0, float& s1, int& i1,
                                       float v, int ix, int lane) {
    unsigned b0 = __ballot_sync(0xffffffffu, s0 > v);
    unsigned b1 = __ballot_sync(0xffffffffu, s1 > v);
    int p = __popc(b0) + __popc(b1);
    float s0p = __shfl_up_sync(0xffffffffu, s0, 1);
    int   i0p = __shfl_up_sync(0xffffffffu, i0, 1);
    float s1p = __shfl_up_sync(0xffffffffu, s1, 1);
    int   i1p = __shfl_up_sync(0xffffffffu, i1, 1);
    float s31 = __shfl_sync(0xffffffffu, s0, 31);
    int   i31 = __shfl_sync(0xffffffffu, i0, 31);
    if (lane == 0) { s1p = s31; i1p = i31; }
    if (lane > p)       { s0 = s0p; i0 = i0p; }
    else if (lane == p) { s0 = v;   i0 = ix;  }
    int r1 = 32 + lane;
    if (r1 > p)         { s1 = s1p; i1 = i1p; }
    else if (r1 == p)   { s1 = v;   i1 = ix;  }
    return __shfl_sync(0xffffffffu, s1, 31);
}

// ---------------- phase B: sequential top-64 scan with exact chunk skip ----------------
// Chunk order identical to the full sequential scan; a chunk is skipped only when
// its strip-max bound proves no element can exceed thr -> candidate set bit-identical.
__global__ void __launch_bounds__(256) select_kernel(
    const __half* __restrict__ sim, const __half* __restrict__ smax,
    int* __restrict__ cand)
{
    int r = (blockIdx.x * 256 + threadIdx.x) >> 5;
    int lane = threadIdx.x & 31;
    if (r >= N_CNT) return;

    // pairwise chunk maxima: chunk it (256 cols) = strips 2it, 2it+1
    const __half2* smrow = reinterpret_cast<const __half2*>(smax + (size_t)r * 128);
    float2 ha = __half22float2(__ldg(&smrow[lane]));        // strips 2*lane, 2*lane+1
    float2 hb = __half22float2(__ldg(&smrow[32 + lane]));   // strips 64+2*lane, 64+2*lane+1
    float pm0 = fmaxf(ha.x, ha.y);   // chunk  lane
    float pm1 = fmaxf(hb.x, hb.y);   // chunk  32+lane

    const uint4* rp = reinterpret_cast<const uint4*>(sim + (size_t)r * N_CNT);
    float s0 = -INFINITY, s1 = -INFINITY;
    int i0 = 0, i1 = 0;
    float thr = -INFINITY;

    for (int it = 0; it < 64; it++) {
        float pmax = __shfl_sync(0xffffffffu, (it < 32) ? pm0 : pm1, it & 31);
        if (!(pmax > thr)) continue;   // exact skip: no element can beat rank-63
        uint4 raw = __ldg(&rp[it * 32 + lane]);
        __half2* h = reinterpret_cast<__half2*>(&raw);
        float2 p0 = __half22float2(h[0]);
        float2 p1 = __half22float2(h[1]);
        float2 p2 = __half22float2(h[2]);
        float2 p3 = __half22float2(h[3]);
        float mxA = fmaxf(fmaxf(p0.x, p0.y), fmaxf(p1.x, p1.y));
        float mxB = fmaxf(fmaxf(p2.x, p2.y), fmaxf(p3.x, p3.y));
        unsigned mA = __ballot_sync(0xffffffffu, mxA > thr);
        unsigned mB = __ballot_sync(0xffffffffu, mxB > thr);
        while (mA) {
            int src = __ffs(mA) - 1;
            mA &= mA - 1;
            float w0 = __shfl_sync(0xffffffffu, p0.x, src);
            float w1 = __shfl_sync(0xffffffffu, p0.y, src);
            float w2 = __shfl_sync(0xffffffffu, p1.x, src);
            float w3 = __shfl_sync(0xffffffffu, p1.y, src);
            int cb = it * 256 + src * 8;
            if (w0 > thr) thr = ins64(s0, i0, s1, i1, w0, cb + 0, lane);
            if (w1 > thr) thr = ins64(s0, i0, s1, i1, w1, cb + 1, lane);
            if (w2 > thr) thr = ins64(s0, i0, s1, i1, w2, cb + 2, lane);
            if (w3 > thr) thr = ins64(s0, i0, s1, i1, w3, cb + 3, lane);
        }
        while (mB) {
            int src = __ffs(mB) - 1;
            mB &= mB - 1;
            float w0 = __shfl_sync(0xffffffffu, p2.x, src);
            float w1 = __shfl_sync(0xffffffffu, p2.y, src);
            float w2 = __shfl_sync(0xffffffffu, p3.x, src);
            float w3 = __shfl_sync(0xffffffffu, p3.y, src);
            int cb = it * 256 + src * 8 + 4;
            if (w0 > thr) thr = ins64(s0, i0, s1, i1, w0, cb + 0, lane);
            if (w1 > thr) thr = ins64(s0, i0, s1, i1, w1, cb + 1, lane);
            if (w2 > thr) thr = ins64(s0, i0, s1, i1, w2, cb + 2, lane);
            if (w3 > thr) thr = ins64(s0, i0, s1, i1, w3, cb + 3, lane);
        }
    }
    cand[r * NCAND + lane] = i0;
    cand[r * NCAND + 32 + lane] = i1;
}

// ---------------- fp32 rescore of 64 candidates -> exact top-32 set ----------------
__global__ void __launch_bounds__(256) rescore_kernel(
    const float* __restrict__ ego, const int* __restrict__ cand, int* __restrict__ topk)
{
    __shared__ float rsh[8 * 128];
    __shared__ int   csh[8 * NCAND];
    int tid = threadIdx.x, lane = tid & 31, w = tid >> 5;
    int Rbase = blockIdx.x * 8;
    reinterpret_cast<float4*>(rsh)[tid] =
        reinterpret_cast<const float4*>(ego + (size_t)Rbase * D_DIM)[tid];
    int R = Rbase + w;
    csh[w * NCAND + lane]      = cand[R * NCAND + lane];
    csh[w * NCAND + 32 + lane] = cand[R * NCAND + 32 + lane];
    __syncthreads();

    float4 a = reinterpret_cast<const float4*>(rsh + w * 128)[lane];
    float val0 = -INFINITY, val1 = -INFINITY;
    int   id0 = 0, id1 = 0;
#pragma unroll
    for (int k = 0; k < NCAND; k++) {
        int ck = csh[w * NCAND + k];
        float4 b = reinterpret_cast<const float4*>(ego)[(size_t)ck * 32 + lane];
        float p = a.x * b.x + a.y * b.y + a.z * b.z + a.w * b.w;
#pragma unroll
        for (int off = 16; off > 0; off >>= 1) p += __shfl_xor_sync(0xffffffffu, p, off);
        if (k < 32) { if (lane == k)      { val0 = p; id0 = ck; } }
        else        { if (lane == k - 32) { val1 = p; id1 = ck; } }
    }
    for (int it = 0; it < K_TOP; it++) {
        float bm = fmaxf(val0, val1); int bl = lane;
#pragma unroll
        for (int off = 16; off > 0; off >>= 1) {
            float om = __shfl_xor_sync(0xffffffffu, bm, off);
            int   ol = __shfl_xor_sync(0xffffffffu, bl, off);
            if (om > bm || (om == bm && ol < bl)) { bm = om; bl = ol; }
        }
        if (lane == bl) {
            if (val1 > val0) { topk[R * K_TOP + it] = id1; val1 = -INFINITY; }
            else             { topk[R * K_TOP + it] = id0; val0 = -INFINITY; }
        }
    }
}

// ---------------- small fp32 GEMM ----------------
__global__ void __launch_bounds__(256, 2) gemm_kernel(
    const float* __restrict__ A, const float* __restrict__ W,
    const float* __restrict__ bias, const float* __restrict__ aux,
    float* __restrict__ out, int trans, int epi)
{
    extern __shared__ float shf[];
    float* Wsh = shf;
    float* Ash = shf + 128 * PAD;
    const int tid = threadIdx.x;
    const int lane = tid & 31;
    const int wid = tid >> 5;
    const int rowbase = blockIdx.x * 32;

    if (!trans) {
        for (int i = tid; i < 128 * 32; i += 256) {
            int c = i >> 5, e4 = i & 31;
            float4 v = *reinterpret_cast<const float4*>(&W[c * D_DIM + e4 * 4]);
            *reinterpret_cast<float4*>(&Wsh[c * PAD + e4 * 4]) = v;
        }
    } else {
        for (int i = tid; i < 128 * 128; i += 256) {
            int e = i >> 7, c = i & 127;
            Wsh[c * PAD + e] = W[i];
        }
    }
    for (int i = tid; i < 32 * 32; i += 256) {
        int r = i >> 5, d4 = i & 31;
        float4 v = *reinterpret_cast<const float4*>(&A[(size_t)(rowbase + r) * D_DIM + d4 * 4]);
        *reinterpret_cast<float4*>(&Ash[r * PAD + d4 * 4]) = v;
    }
    __syncthreads();

    float acc[4][4];
#pragma unroll
    for (int j = 0; j < 4; j++)
#pragma unroll
        for (int k = 0; k < 4; k++) acc[j][k] = 0.0f;

    const float* abase = Ash + (wid * 4) * PAD;
    const float* wbase = Wsh + lane * PAD;
#pragma unroll 8
    for (int d = 0; d < D_DIM; d += 4) {
        float4 a0 = *reinterpret_cast<const float4*>(abase + 0 * PAD + d);
        float4 a1 = *reinterpret_cast<const float4*>(abase + 1 * PAD + d);
        float4 a2 = *reinterpret_cast<const float4*>(abase + 2 * PAD + d);
        float4 a3 = *reinterpret_cast<const float4*>(abase + 3 * PAD + d);
        float4 w0 = *reinterpret_cast<const float4*>(wbase + 0 * PAD + d);
        float4 w1 = *reinterpret_cast<const float4*>(wbase + 32 * PAD + d);
        float4 w2 = *reinterpret_cast<const float4*>(wbase + 64 * PAD + d);
        float4 w3 = *reinterpret_cast<const float4*>(wbase + 96 * PAD + d);
#define DO4(j, av) \
        acc[j][0] += av.x*w0.x + av.y*w0.y + av.z*w0.z + av.w*w0.w; \
        acc[j][1] += av.x*w1.x + av.y*w1.y + av.z*w1.z + av.w*w1.w; \
        acc[j][2] += av.x*w2.x + av.y*w2.y + av.z*w2.z + av.w*w2.w; \
        acc[j][3] += av.x*w3.x + av.y*w3.y + av.z*w3.z + av.w*w3.w;
        DO4(0, a0) DO4(1, a1) DO4(2, a2) DO4(3, a3)
#undef DO4
    }

#pragma unroll
    for (int j = 0; j < 4; j++) {
        int n = rowbase + wid * 4 + j;
#pragma unroll
        for (int k = 0; k < 4; k++) {
            int c = lane + 32 * k;
            float v = acc[j][k];
            if (bias) v += bias[c];
            if (epi == 1) v = tanhf(v);
            else if (epi == 2) v += 0.1f * aux[(size_t)n * D_DIM + c];
            out[(size_t)n * D_DIM + c] = v;
        }
    }
}

// ---------------- attention over top-32 ----------------
__global__ void __launch_bounds__(256) attn_kernel(
    const float* __restrict__ ego, const float* __restrict__ qk,
    const int* __restrict__ topk, float* __restrict__ mix)
{
    int n = (blockIdx.x * 256 + threadIdx.x) >> 5;
    int lane = threadIdx.x & 31;
    if (n >= N_CNT) return;

    float4 qv = *reinterpret_cast<const float4*>(&qk[(size_t)n * D_DIM + lane * 4]);
    int myidx = topk[(size_t)n * K_TOP + lane];
    float myscore = 0.0f;
#pragma unroll 4
    for (int k = 0; k < K_TOP; k++) {
        int id = __shfl_sync(0xffffffffu, myidx, k);
        float4 e = *reinterpret_cast<const float4*>(&ego[(size_t)id * D_DIM + lane * 4]);
        float p = qv.x * e.x + qv.y * e.y + qv.z * e.z + qv.w * e.w;
#pragma unroll
        for (int off = 16; off > 0; off >>= 1) p += __shfl_xor_sync(0xffffffffu, p, off);
        if (lane == k) myscore = p * 0.08838834764831845f;
    }
    float m = myscore;
#pragma unroll
    for (int off = 16; off > 0; off >>= 1) m = fmaxf(m, __shfl_xor_sync(0xffffffffu, m, off));
    float ex = expf(myscore - m);
    float z = ex;
#pragma unroll
    for (int off = 16; off > 0; off >>= 1) z += __shfl_xor_sync(0xffffffffu, z, off);
    float a = ex / z;

    float4 accv = make_float4(0.f, 0.f, 0.f, 0.f);
#pragma unroll 4
    for (int k = 0; k < K_TOP; k++) {
        float ak = __shfl_sync(0xffffffffu, a, k);
        int id = __shfl_sync(0xffffffffu, myidx, k);
        float4 e = *reinterpret_cast<const float4*>(&ego[(size_t)id * D_DIM + lane * 4]);
        accv.x += ak * e.x; accv.y += ak * e.y; accv.z += ak * e.z; accv.w += ak * e.w;
    }
    *reinterpret_cast<float4*>(&mix[(size_t)n * D_DIM + lane * 4]) = accv;
}

// ---------------- fusion column softmax ----------------
__global__ void colinit_kernel(unsigned* cmax, float* csum) {
    int i = threadIdx.x;
    if (i < 2 * D_DIM) { cmax[i] = f2key(-1e30f); csum[i] = 0.0f; }
}
__global__ void __launch_bounds__(128) colmax_kernel(const float* __restrict__ t, unsigned* __restrict__ cmax) {
    int d = threadIdx.x;
    int r0 = blockIdx.x * 128;
    float m = -1e30f;
    for (int r = r0; r < r0 + 128; r++) m = fmaxf(m, t[(size_t)r * D_DIM + d]);
    atomicMax(&cmax[d], f2key(m));
}
__global__ void __launch_bounds__(128) colsum_kernel(const float* __restrict__ t,
                                                     const unsigned* __restrict__ cmax,
                                                     float* __restrict__ csum) {
    int d = threadIdx.x;
    int r0 = blockIdx.x * 128;
    float mx = key2f(cmax[d]);
    float s = 0.0f;
    for (int r = r0; r < r0 + 128; r++) s += expf(t[(size_t)r * D_DIM + d] - mx);
    atomicAdd(&csum[d], s);
}
__global__ void fusion_kernel(const float* __restrict__ t1, const float* __restrict__ t2,
                              const unsigned* __restrict__ cmax, const float* __restrict__ csum,
                              const float* __restrict__ all, const float* __restrict__ atten,
                              float* __restrict__ out, int n) {
    int i = blockIdx.x * blockDim.x + threadIdx.x;
    if (i >= n) return;
    int d = i & (D_DIM - 1);
    float w1 = expf(t1[i] - key2f(cmax[d]))         / csum[d];
    float w2 = expf(t2[i] - key2f(cmax[D_DIM + d])) / csum[D_DIM + d];
    out[i] = w1 * all[i] + w2 * atten[i];
}

// ---------------- launch ----------------
extern "C" void kernel_launch(void* const* d_in, const int* in_sizes, int n_in,
                              void* d_out, int out_size) {
    const float* user = (const float*)d_in[0];
    const float* item = (const float*)d_in[1];
    const int*   rows = (const int*)d_in[2];
    const int*   cols = (const int*)d_in[3];
    const float* vals = (const float*)d_in[4];
    const float* wq   = (const float*)d_in[5];
    const float* bq   = (const float*)d_in[6];
    const float* wk   = (const float*)d_in[7];
    const float* wv   = (const float*)d_in[9];
    const float* bv   = (const float*)d_in[10];
    const float* fw   = (const float*)d_in[11];
    const float* fb   = (const float*)d_in[12];

    const int ND = N_CNT * D_DIM;
    const int SMEM = (128 * PAD + 32 * PAD) * 4;
    cudaFuncSetAttribute(gemm_kernel, cudaFuncAttributeMaxDynamicSharedMemorySize, SMEM);
    cudaFuncSetAttribute(simgemm_kernel, cudaFuncAttributeMaxDynamicSharedMemorySize, GEMM_SMEM);

    float *bufA, *bufB, *ego, *qbuf, *qkb, *mixb, *t1, *t2, *csum, *eval, *scalef, *muf, *cvec;
    __half *egoh, *simp, *smaxp;
    int *cand, *topk, *rowstart, *cursor, *ecol;
    unsigned *cmax, *skey;
    cudaGetSymbolAddress((void**)&bufA, g_bufA);
    cudaGetSymbolAddress((void**)&bufB, g_bufB);
    cudaGetSymbolAddress((void**)&ego,  g_ego);
    cudaGetSymbolAddress((void**)&qbuf, g_q);
    cudaGetSymbolAddress((void**)&qkb,  g_qk);
    cudaGetSymbolAddress((void**)&mixb, g_mix);
    cudaGetSymbolAddress((void**)&t1,   g_t1);
    cudaGetSymbolAddress((void**)&t2,   g_t2);
    cudaGetSymbolAddress((void**)&egoh, g_egoh);
    cudaGetSymbolAddress((void**)&simp, g_sim);
    cudaGetSymbolAddress((void**)&smaxp, g_smax);
    cudaGetSymbolAddress((void**)&cand, g_cand);
    cudaGetSymbolAddress((void**)&topk, g_topk);
    cudaGetSymbolAddress((void**)&cmax, g_cmax);
    cudaGetSymbolAddress((void**)&csum, g_csum);
    cudaGetSymbolAddress((void**)&skey, g_skey);
    cudaGetSymbolAddress((void**)&scalef, g_scale);
    cudaGetSymbolAddress((void**)&muf, g_mu);
    cudaGetSymbolAddress((void**)&cvec, g_cvec);
    cudaGetSymbolAddress((void**)&rowstart, g_rowstart);
    cudaGetSymbolAddress((void**)&cursor, g_cursor);
    cudaGetSymbolAddress((void**)&ecol, g_ecol);
    cudaGetSymbolAddress((void**)&eval, g_eval);

    float* outAll = (float*)d_out;
    float* outAtt = outAll + ND;
    float* outFus = outAll + 2 * ND;

    const int ZB = ND / 256;
    const int EB = E_CNT / 256;
    const int RB = (N_CNT * 32) / 256;

    // CSR build (atomic-free SpMM afterwards)
    zero_int_kernel<<<N_CNT / 256, 256>>>(cursor, N_CNT);
    hist_kernel<<<EB, 256>>>(rows, cursor);
    scan_kernel<<<1, 512>>>(cursor, rowstart, cursor);
    scatter_kernel<<<EB, 256>>>(rows, cols, vals, cursor, ecol, eval);

    // 3 SpMM layers
    spmm_csr_kernel<<<RB, 256>>>(user, item, rowstart, ecol, eval, bufA);
    spmm_csr_kernel<<<RB, 256>>>(bufA, bufA + U_CNT * D_DIM, rowstart, ecol, eval, bufB);
    spmm_csr_kernel<<<RB, 256>>>(bufB, bufB + U_CNT * D_DIM, rowstart, ecol, eval, ego);
    mean3_kernel<<<ZB, 256>>>(bufA, bufB, ego, outAll, ND);

    // row-offset stats (+ fused fp16 convert)
    zero_int_kernel<<<1, 32>>>((int*)skey, 2);
    zero_int_kernel<<<1, 128>>>((int*)muf, D_DIM);
    colmean_kernel<<<N_CNT / 128, 128>>>(ego, muf);
    rowdot_kernel<<<RB, 256>>>(ego, muf, cvec, skey, egoh);
    scale2_kernel<<<1, 1>>>(skey, scalef);

    // symmetric offset-removed fp16 sim GEMM (+strip max) -> skip-scan top-64 -> fp32 rescore
    simgemm_kernel<<<dim3(N_CNT / 128, N_CNT / 128), 256, GEMM_SMEM>>>(egoh, simp, smaxp, scalef, cvec);
    select_kernel<<<RB, 256>>>(simp, smaxp, cand);
    rescore_kernel<<<N_CNT / 8, 256>>>(ego, cand, topk);

    // qk = ego @ (wq^T wk) + bq@wk   (folded weights)
    wqk_kernel<<<128, 128>>>(wq, wk, bq, qbuf);
    gemm_kernel<<<N_CNT / 32, 256, SMEM>>>(ego, qbuf, qbuf + D_DIM * D_DIM, nullptr, qkb, 1, 0);
    attn_kernel<<<RB, 256>>>(ego, qkb, topk, mixb);
    gemm_kernel<<<N_CNT / 32, 256, SMEM>>>(mixb, wv, bv, ego, outAtt, 0, 2);

    gemm_kernel<<<N_CNT / 32, 256, SMEM>>>(outAll, fw, fb, nullptr, t1, 0, 1);
    gemm_kernel<<<N_CNT / 32, 256, SMEM>>>(outAtt, fw, fb, nullptr, t2, 0, 1);
    colinit_kernel<<<1, 256>>>(cmax, csum);
    colmax_kernel<<<N_CNT / 128, 128>>>(t1, cmax);
    colmax_kernel<<<N_CNT / 128, 128>>>(t2, cmax + D_DIM);
    colsum_kernel<<<N_CNT / 128, 128>>>(t1, cmax, csum);
    colsum_kernel<<<N_CNT / 128, 128>>>(t2, cmax + D_DIM, csum + D_DIM);
    fusion_kernel<<<ZB, 256>>>(t1, t2, cmax, csum, outAll, outAtt, outFus, ND);
}

// round 14
// speedup vs baseline: 1.0949x; 1.0836x over previous
#include <cuda_runtime.h>
#include <cuda_fp16.h>
#include <math.h>

#define U_CNT 8192
#define N_CNT 16384
#define D_DIM 128
#define E_CNT 524288
#define K_TOP 32
#define NCAND 64
#define PAD   132

// ---------------- scratch (device globals; no allocation) ----------------
__device__ float g_bufA[N_CNT * D_DIM];
__device__ float g_bufB[N_CNT * D_DIM];
__device__ float g_ego [N_CNT * D_DIM];
__device__ float g_q   [N_CNT * D_DIM];   // reused: M = wq^T@wk (16384) + b2 (128)
__device__ float g_qk  [N_CNT * D_DIM];
__device__ float g_mix [N_CNT * D_DIM];
__device__ __half g_egoh[N_CNT * D_DIM];
__device__ __half g_sim[(size_t)N_CNT * N_CNT];   // 512 MB scratch; tail reused as fp32 t-buffer
__device__ int   g_cand[N_CNT * NCAND];
__device__ unsigned g_cmax[2 * D_DIM];
__device__ float    g_csum[2 * D_DIM];
__device__ unsigned g_skey[2];       // [0]=max||ego||^2, [1]=max||ego-mu||^2
__device__ float    g_scale[1];
__device__ float    g_mu[D_DIM];
__device__ float    g_cvec[N_CNT];   // c_i = <ego_i, mu>
// CSR scratch
__device__ int   g_rowstart[N_CNT + 1];
__device__ int   g_cursor[N_CNT];
__device__ int   g_ecol[E_CNT];
__device__ float g_eval[E_CNT];

// ---------------- helpers ----------------
__device__ __forceinline__ unsigned f2key(float f) {
    int i = __float_as_int(f);
    return (unsigned)i ^ (unsigned)((i >> 31) | 0x80000000);
}
__device__ __forceinline__ float key2f(unsigned k) {
    int i;
    if (k & 0x80000000u) i = (int)(k ^ 0x80000000u);
    else                 i = (int)(~k);
    return __int_as_float(i);
}
__device__ __forceinline__ unsigned smem_u32(const void* p) {
    return (unsigned)__cvta_generic_to_shared(p);
}
__device__ __forceinline__ unsigned h2u(__half2 v) {
    return *reinterpret_cast<unsigned*>(&v);
}
__device__ __forceinline__ void ldmat4(unsigned& r0, unsigned& r1, unsigned& r2, unsigned& r3, unsigned a) {
    asm volatile("ldmatrix.sync.aligned.m8n8.x4.shared.b16 {%0,%1,%2,%3}, [%4];"
                 : "=r"(r0), "=r"(r1), "=r"(r2), "=r"(r3) : "r"(a));
}
__device__ __forceinline__ void mma16816(float* c, unsigned a0, unsigned a1, unsigned a2, unsigned a3,
                                         unsigned b0, unsigned b1) {
    asm volatile("mma.sync.aligned.m16n8k16.row.col.f32.f16.f16.f32 "
                 "{%0,%1,%2,%3}, {%4,%5,%6,%7}, {%8,%9}, {%0,%1,%2,%3};"
                 : "+f"(c[0]), "+f"(c[1]), "+f"(c[2]), "+f"(c[3])
                 : "r"(a0), "r"(a1), "r"(a2), "r"(a3), "r"(b0), "r"(b1));
}
__device__ __forceinline__ void cp16(unsigned dst, const void* src) {
    asm volatile("cp.async.cg.shared.global [%0], [%1], 16;" :: "r"(dst), "l"(src));
}
#define CP_COMMIT() asm volatile("cp.async.commit_group;" ::: "memory")
#define CP_WAIT0()  asm volatile("cp.async.wait_group 0;" ::: "memory")

// ---------------- trivial kernels ----------------
__global__ void zero_int_kernel(int* __restrict__ p, int n) {
    int i = blockIdx.x * blockDim.x + threadIdx.x;
    if (i < n) p[i] = 0;
}
__global__ void mean3_kernel(const float* __restrict__ a, const float* __restrict__ b,
                             const float* __restrict__ c, float* __restrict__ out, int n) {
    int i = blockIdx.x * blockDim.x + threadIdx.x;
    if (i < n) out[i] = (a[i] + b[i] + c[i]) * (1.0f / 3.0f);
}
// column mean accumulate (scaled by 1/N inline)
__global__ void __launch_bounds__(128) colmean_kernel(const float* __restrict__ ego,
                                                      float* __restrict__ mu) {
    int d = threadIdx.x;
    int r0 = blockIdx.x * 128;
    float s = 0.0f;
    for (int r = r0; r < r0 + 128; r++) s += ego[(size_t)r * D_DIM + d];
    atomicAdd(&mu[d], s * (1.0f / N_CNT));
}
// fused row stats + fp16 convert
__global__ void __launch_bounds__(256) rowdot_kernel(const float* __restrict__ ego,
                                                     const float* __restrict__ mu,
                                                     float* __restrict__ c,
                                                     unsigned* __restrict__ keys,
                                                     __half* __restrict__ egoh) {
    int r = (blockIdx.x * 256 + threadIdx.x) >> 5;
    int lane = threadIdx.x & 31;
    float4 v = *reinterpret_cast<const float4*>(&ego[(size_t)r * D_DIM + lane * 4]);
    float4 m = *reinterpret_cast<const float4*>(&mu[lane * 4]);
    uint2 oh;
    oh.x = h2u(__floats2half2_rn(v.x, v.y));
    oh.y = h2u(__floats2half2_rn(v.z, v.w));
    *reinterpret_cast<uint2*>(&egoh[(size_t)r * D_DIM + lane * 4]) = oh;
    float nrm = v.x * v.x + v.y * v.y + v.z * v.z + v.w * v.w;
    float dot = v.x * m.x + v.y * m.y + v.z * m.z + v.w * m.w;
    float dx = v.x - m.x, dy = v.y - m.y, dz = v.z - m.z, dw = v.w - m.w;
    float dev = dx * dx + dy * dy + dz * dz + dw * dw;
#pragma unroll
    for (int off = 16; off > 0; off >>= 1) {
        nrm += __shfl_xor_sync(0xffffffffu, nrm, off);
        dot += __shfl_xor_sync(0xffffffffu, dot, off);
        dev += __shfl_xor_sync(0xffffffffu, dev, off);
    }
    if (lane == 0) {
        c[r] = dot;
        atomicMax(&keys[0], f2key(nrm));
        atomicMax(&keys[1], f2key(dev));
    }
}
__global__ void scale2_kernel(const unsigned* __restrict__ skey, float* __restrict__ scale) {
    float a = sqrtf(fmaxf(key2f(skey[0]), 1e-30f));
    float b = sqrtf(fmaxf(key2f(skey[1]), 1e-30f));
    *scale = 16384.0f / fmaxf(a * b, 1e-30f);
}
// M[e][c] = sum_d wq[d][e]*wk[d][c] ; b2[c] = sum_d bq[d]*wk[d][c]
__global__ void wqk_kernel(const float* __restrict__ wq, const float* __restrict__ wk,
                           const float* __restrict__ bq, float* __restrict__ M) {
    int e = blockIdx.x, c = threadIdx.x;
    float s = 0.0f;
    for (int d = 0; d < D_DIM; d++) s += wq[d * D_DIM + e] * wk[d * D_DIM + c];
    M[e * D_DIM + c] = s;
    if (e == 0) {
        float b = 0.0f;
        for (int d = 0; d < D_DIM; d++) b += bq[d] * wk[d * D_DIM + c];
        M[D_DIM * D_DIM + c] = b;
    }
}

// ---------------- CSR build ----------------
__global__ void hist_kernel(const int* __restrict__ rows, int* __restrict__ cnt) {
    int e = blockIdx.x * blockDim.x + threadIdx.x;
    if (e < E_CNT) atomicAdd(&cnt[rows[e]], 1);
}
__global__ void __launch_bounds__(512) scan_kernel(int* __restrict__ cnt,
                                                   int* __restrict__ rowstart,
                                                   int* __restrict__ cursor) {
    __shared__ int ssum[512];
    int t = threadIdx.x;
    int base = t * 32;
    int local[32];
    int s = 0;
#pragma unroll
    for (int j = 0; j < 32; j++) { local[j] = cnt[base + j]; s += local[j]; }
    ssum[t] = s;
    __syncthreads();
    for (int off = 1; off < 512; off <<= 1) {
        int v = (t >= off) ? ssum[t - off] : 0;
        __syncthreads();
        ssum[t] += v;
        __syncthreads();
    }
    int run = (t > 0) ? ssum[t - 1] : 0;
#pragma unroll
    for (int j = 0; j < 32; j++) {
        rowstart[base + j] = run;
        cursor[base + j] = run;
        run += local[j];
    }
    if (t == 511) rowstart[N_CNT] = run;
}
__global__ void scatter_kernel(const int* __restrict__ rows, const int* __restrict__ cols,
                               const float* __restrict__ vals, int* __restrict__ cursor,
                               int* __restrict__ ecol, float* __restrict__ eval) {
    int e = blockIdx.x * blockDim.x + threadIdx.x;
    if (e >= E_CNT) return;
    int pos = atomicAdd(&cursor[rows[e]], 1);
    ecol[pos] = cols[e];
    eval[pos] = vals[e];
}
// warp per row, no atomics
__global__ void __launch_bounds__(256) spmm_csr_kernel(
    const float* __restrict__ xu, const float* __restrict__ xi,
    const int* __restrict__ rowstart, const int* __restrict__ ecol,
    const float* __restrict__ eval, float* __restrict__ y)
{
    int r = (blockIdx.x * 256 + threadIdx.x) >> 5;
    int lane = threadIdx.x & 31;
    if (r >= N_CNT) return;
    int s = rowstart[r], e = rowstart[r + 1];
    float4 acc = make_float4(0.f, 0.f, 0.f, 0.f);
#pragma unroll 2
    for (int i = s; i < e; i++) {
        int c = __ldg(&ecol[i]);
        float v = __ldg(&eval[i]);
        const float* src = (c < U_CNT) ? (xu + (size_t)c * D_DIM)
                                       : (xi + (size_t)(c - U_CNT) * D_DIM);
        float4 x = *reinterpret_cast<const float4*>(src + lane * 4);
        acc.x += v * x.x; acc.y += v * x.y; acc.z += v * x.z; acc.w += v * x.w;
    }
    *reinterpret_cast<float4*>(y + (size_t)r * D_DIM + lane * 4) = acc;
}

// ---------------- phase A: symmetric sim GEMM (fp16 HMMA, row-offset removed) ----------------
#define TSH_OFF  67584
#define TSH_STR  136   // halfs; 272B row = 16B-aligned
#define GEMM_SMEM 102400

__global__ void __launch_bounds__(256, 2) simgemm_kernel(
    const __half* __restrict__ egh, __half* __restrict__ sim,
    const float* __restrict__ scalep, const float* __restrict__ cvec)
{
    const int bx = blockIdx.x, by = blockIdx.y;
    if (bx < by) return;          // upper triangle only
    extern __shared__ char sh[];
    const int tid = threadIdx.x;
    const int lane = tid & 31;
    const int wid = tid >> 5;
    const int wm = wid >> 1, wn = wid & 1;
    const int rowbase = by * 128;
    const int colbase = bx * 128;
    float* simf = (float*)sh;
    __half* tsh = (__half*)(sh + TSH_OFF);
    const unsigned aBase = smem_u32(sh);
    const unsigned bBase = aBase + 34816;
    const float scl = *scalep;

#pragma unroll
    for (int i = 0; i < 8; i++) {
        int ch = tid + i * 256;
        int row = ch >> 4, off = ch & 15;
        cp16(aBase + row * 272 + off * 16, egh + (size_t)(rowbase + row) * D_DIM + off * 8);
        cp16(bBase + row * 272 + off * 16, egh + (size_t)(colbase + row) * D_DIM + off * 8);
    }
    CP_COMMIT();
    CP_WAIT0();
    __syncthreads();

    float acc[2][8][4];
#pragma unroll
    for (int mt = 0; mt < 2; mt++)
#pragma unroll
        for (int nt = 0; nt < 8; nt++)
#pragma unroll
            for (int q = 0; q < 4; q++) acc[mt][nt][q] = 0.0f;

#pragma unroll
    for (int ks = 0; ks < 8; ks++) {
        unsigned a0[4], a1[4];
        ldmat4(a0[0], a0[1], a0[2], a0[3],
               aBase + (wm * 32 + 0 + (lane & 15)) * 272 + ks * 32 + (lane >> 4) * 16);
        ldmat4(a1[0], a1[1], a1[2], a1[3],
               aBase + (wm * 32 + 16 + (lane & 15)) * 272 + ks * 32 + (lane >> 4) * 16);
#pragma unroll
        for (int np = 0; np < 4; np++) {
            unsigned b0, b1, b2, b3;
            ldmat4(b0, b1, b2, b3,
                   bBase + (wn * 64 + np * 16 + ((lane >> 4) & 1) * 8 + (lane & 7)) * 272
                        + ks * 32 + ((lane >> 3) & 1) * 16);
            mma16816(acc[0][2 * np + 0], a0[0], a0[1], a0[2], a0[3], b0, b1);
            mma16816(acc[1][2 * np + 0], a1[0], a1[1], a1[2], a1[3], b0, b1);
            mma16816(acc[0][2 * np + 1], a0[0], a0[1], a0[2], a0[3], b2, b3);
            mma16816(acc[1][2 * np + 1], a1[0], a1[1], a1[2], a1[3], b2, b3);
        }
    }
#pragma unroll
    for (int mt = 0; mt < 2; mt++)
#pragma unroll
        for (int nt = 0; nt < 8; nt++)
#pragma unroll
            for (int q = 0; q < 4; q++) acc[mt][nt][q] *= scl;

    __syncthreads();   // operands dead; simf aliases them

    {
        int g = lane >> 2, t4 = lane & 3;
#pragma unroll
        for (int mt = 0; mt < 2; mt++)
#pragma unroll
            for (int nt = 0; nt < 8; nt++) {
                int r0 = wm * 32 + mt * 16 + g;
                int c  = wn * 64 + nt * 8 + 2 * t4;
                *reinterpret_cast<float2*>(&simf[r0 * 132 + c]) =
                    make_float2(acc[mt][nt][0], acc[mt][nt][1]);
                *reinterpret_cast<float2*>(&simf[(r0 + 8) * 132 + c]) =
                    make_float2(acc[mt][nt][2], acc[mt][nt][3]);
            }
    }
    __syncthreads();

    // normal store (fp16, coalesced); subtract row-offset c_i*scl
#pragma unroll
    for (int i = tid; i < 128 * 16; i += 256) {
        int row = i >> 4, seg = i & 15;
        float csub = __ldg(&cvec[rowbase + row]) * scl;
        const float* p = &simf[row * 132 + seg * 8];
        float4 f0 = *reinterpret_cast<const float4*>(p);
        float4 f1 = *reinterpret_cast<const float4*>(p + 4);
        uint4 o;
        o.x = h2u(__floats2half2_rn(f0.x - csub, f0.y - csub));
        o.y = h2u(__floats2half2_rn(f0.z - csub, f0.w - csub));
        o.z = h2u(__floats2half2_rn(f1.x - csub, f1.y - csub));
        o.w = h2u(__floats2half2_rn(f1.z - csub, f1.w - csub));
        *reinterpret_cast<uint4*>(&sim[(size_t)(rowbase + row) * N_CNT + colbase + seg * 8]) = o;
    }

    if (bx != by) {
        // transposed restage: mirror row is colbase+ci -> subtract c_j*scl
#pragma unroll
        for (int i = tid; i < 2048; i += 256) {
            int ci = i & 127, seg = i >> 7;
            float csub = __ldg(&cvec[colbase + ci]) * scl;
            float v[8];
#pragma unroll
            for (int k = 0; k < 8; k++) v[k] = simf[(seg * 8 + k) * 132 + ci] - csub;
            uint4 o;
            o.x = h2u(__floats2half2_rn(v[0], v[1]));
            o.y = h2u(__floats2half2_rn(v[2], v[3]));
            o.z = h2u(__floats2half2_rn(v[4], v[5]));
            o.w = h2u(__floats2half2_rn(v[6], v[7]));
            *reinterpret_cast<uint4*>(&tsh[ci * TSH_STR + seg * 8]) = o;
        }
        __syncthreads();
#pragma unroll
        for (int i = tid; i < 2048; i += 256) {
            int ci = i >> 4, seg = i & 15;
            uint4 o = *reinterpret_cast<const uint4*>(&tsh[ci * TSH_STR + seg * 8]);
            *reinterpret_cast<uint4*>(&sim[(size_t)(colbase + ci) * N_CNT + rowbase + seg * 8]) = o;
        }
    }
}

// ---------------- sorted top-64 insert (warp-distributed, descending) ----------------
__device__ __forceinline__ float ins64(float& s0, int& i0, float& s1, int& i1,
                                       float v, int ix, int lane) {
    unsigned b0 = __ballot_sync(0xffffffffu, s0 > v);
    unsigned b1 = __ballot_sync(0xffffffffu, s1 > v);
    int p = __popc(b0) + __popc(b1);
    float s0p = __shfl_up_sync(0xffffffffu, s0, 1);
    int   i0p = __shfl_up_sync(0xffffffffu, i0, 1);
    float s1p = __shfl_up_sync(0xffffffffu, s1, 1);
    int   i1p = __shfl_up_sync(0xffffffffu, i1, 1);
    float s31 = __shfl_sync(0xffffffffu, s0, 31);
    int   i31 = __shfl_sync(0xffffffffu, i0, 31);
    if (lane == 0) { s1p = s31; i1p = i31; }
    if (lane > p)       { s0 = s0p; i0 = i0p; }
    else if (lane == p) { s0 = v;   i0 = ix;  }
    int r1 = 32 + lane;
    if (r1 > p)         { s1 = s1p; i1 = i1p; }
    else if (r1 == p)   { s1 = v;   i1 = ix;  }
    return __shfl_sync(0xffffffffu, s1, 31);
}

// ---------------- phase B: warp-per-row sequential top-64 scan ----------------
__global__ void __launch_bounds__(256) select_kernel(
    const __half* __restrict__ sim, int* __restrict__ cand)
{
    int r = (blockIdx.x * 256 + threadIdx.x) >> 5;
    int lane = threadIdx.x & 31;
    if (r >= N_CNT) return;
    const uint4* rp = reinterpret_cast<const uint4*>(sim + (size_t)r * N_CNT);

    float s0 = -INFINITY, s1 = -INFINITY;
    int i0 = 0, i1 = 0;
    float thr = -INFINITY;

    uint4 nxt = __ldg(&rp[lane]);
    for (int it = 0; it < 64; it++) {
        uint4 raw = nxt;
        if (it < 63) nxt = __ldg(&rp[(it + 1) * 32 + lane]);
        __half2* h = reinterpret_cast<__half2*>(&raw);
        float2 p0 = __half22float2(h[0]);
        float2 p1 = __half22float2(h[1]);
        float2 p2 = __half22float2(h[2]);
        float2 p3 = __half22float2(h[3]);
        float mxA = fmaxf(fmaxf(p0.x, p0.y), fmaxf(p1.x, p1.y));
        float mxB = fmaxf(fmaxf(p2.x, p2.y), fmaxf(p3.x, p3.y));
        unsigned mA = __ballot_sync(0xffffffffu, mxA > thr);
        unsigned mB = __ballot_sync(0xffffffffu, mxB > thr);
        while (mA) {
            int src = __ffs(mA) - 1;
            mA &= mA - 1;
            float w0 = __shfl_sync(0xffffffffu, p0.x, src);
            float w1 = __shfl_sync(0xffffffffu, p0.y, src);
            float w2 = __shfl_sync(0xffffffffu, p1.x, src);
            float w3 = __shfl_sync(0xffffffffu, p1.y, src);
            int cb = it * 256 + src * 8;
            if (w0 > thr) thr = ins64(s0, i0, s1, i1, w0, cb + 0, lane);
            if (w1 > thr) thr = ins64(s0, i0, s1, i1, w1, cb + 1, lane);
            if (w2 > thr) thr = ins64(s0, i0, s1, i1, w2, cb + 2, lane);
            if (w3 > thr) thr = ins64(s0, i0, s1, i1, w3, cb + 3, lane);
        }
        while (mB) {
            int src = __ffs(mB) - 1;
            mB &= mB - 1;
            float w0 = __shfl_sync(0xffffffffu, p2.x, src);
            float w1 = __shfl_sync(0xffffffffu, p2.y, src);
            float w2 = __shfl_sync(0xffffffffu, p3.x, src);
            float w3 = __shfl_sync(0xffffffffu, p3.y, src);
            int cb = it * 256 + src * 8 + 4;
            if (w0 > thr) thr = ins64(s0, i0, s1, i1, w0, cb + 0, lane);
            if (w1 > thr) thr = ins64(s0, i0, s1, i1, w1, cb + 1, lane);
            if (w2 > thr) thr = ins64(s0, i0, s1, i1, w2, cb + 2, lane);
            if (w3 > thr) thr = ins64(s0, i0, s1, i1, w3, cb + 3, lane);
        }
    }
    cand[r * NCAND + lane] = i0;
    cand[r * NCAND + 32 + lane] = i1;
}

// ---------------- fused: fp32 rescore (top-32 set) + attention mix ----------------
__global__ void __launch_bounds__(256) rescore_attn_kernel(
    const float* __restrict__ ego, const float* __restrict__ qk,
    const int* __restrict__ cand, float* __restrict__ mix)
{
    __shared__ float rsh[8 * 128];
    __shared__ float qsh[8 * 128];
    __shared__ int   csh[8 * NCAND];
    int tid = threadIdx.x, lane = tid & 31, w = tid >> 5;
    int Rbase = blockIdx.x * 8;
    reinterpret_cast<float4*>(rsh)[tid] =
        reinterpret_cast<const float4*>(ego + (size_t)Rbase * D_DIM)[tid];
    reinterpret_cast<float4*>(qsh)[tid] =
        reinterpret_cast<const float4*>(qk + (size_t)Rbase * D_DIM)[tid];
    int R = Rbase + w;
    csh[w * NCAND + lane]      = cand[R * NCAND + lane];
    csh[w * NCAND + 32 + lane] = cand[R * NCAND + 32 + lane];
    __syncthreads();

    float4 a  = reinterpret_cast<const float4*>(rsh + w * 128)[lane];
    float4 qv = reinterpret_cast<const float4*>(qsh + w * 128)[lane];

    // fp32 rescore of 64 candidates
    float val0 = -INFINITY, val1 = -INFINITY;
    int   id0 = 0, id1 = 0;
#pragma unroll
    for (int k = 0; k < NCAND; k++) {
        int ck = csh[w * NCAND + k];
        float4 b = reinterpret_cast<const float4*>(ego)[(size_t)ck * 32 + lane];
        float p = a.x * b.x + a.y * b.y + a.z * b.z + a.w * b.w;
#pragma unroll
        for (int off = 16; off > 0; off >>= 1) p += __shfl_xor_sync(0xffffffffu, p, off);
        if (k < 32) { if (lane == k)      { val0 = p; id0 = ck; } }
        else        { if (lane == k - 32) { val1 = p; id1 = ck; } }
    }
    // iterative top-32 selection; lane `it` keeps pick `it` (same order as before)
    int myidx = 0;
    for (int it = 0; it < K_TOP; it++) {
        float bm = fmaxf(val0, val1); int bl = lane;
#pragma unroll
        for (int off = 16; off > 0; off >>= 1) {
            float om = __shfl_xor_sync(0xffffffffu, bm, off);
            int   ol = __shfl_xor_sync(0xffffffffu, bl, off);
            if (om > bm || (om == bm && ol < bl)) { bm = om; bl = ol; }
        }
        int choice = (val1 > val0) ? id1 : id0;
        int selid = __shfl_sync(0xffffffffu, choice, bl);
        if (lane == bl) {
            if (val1 > val0) val1 = -INFINITY; else val0 = -INFINITY;
        }
        if (lane == it) myidx = selid;
    }

    // attention over the 32 selected (identical math to prior attn_kernel)
    float myscore = 0.0f;
#pragma unroll 4
    for (int k = 0; k < K_TOP; k++) {
        int id = __shfl_sync(0xffffffffu, myidx, k);
        float4 e = *reinterpret_cast<const float4*>(&ego[(size_t)id * D_DIM + lane * 4]);
        float p = qv.x * e.x + qv.y * e.y + qv.z * e.z + qv.w * e.w;
#pragma unroll
        for (int off = 16; off > 0; off >>= 1) p += __shfl_xor_sync(0xffffffffu, p, off);
        if (lane == k) myscore = p * 0.08838834764831845f;
    }
    float m = myscore;
#pragma unroll
    for (int off = 16; off > 0; off >>= 1) m = fmaxf(m, __shfl_xor_sync(0xffffffffu, m, off));
    float ex = expf(myscore - m);
    float z = ex;
#pragma unroll
    for (int off = 16; off > 0; off >>= 1) z += __shfl_xor_sync(0xffffffffu, z, off);
    float aw = ex / z;

    float4 accv = make_float4(0.f, 0.f, 0.f, 0.f);
#pragma unroll 4
    for (int k = 0; k < K_TOP; k++) {
        float ak = __shfl_sync(0xffffffffu, aw, k);
        int id = __shfl_sync(0xffffffffu, myidx, k);
        float4 e = *reinterpret_cast<const float4*>(&ego[(size_t)id * D_DIM + lane * 4]);
        accv.x += ak * e.x; accv.y += ak * e.y; accv.z += ak * e.z; accv.w += ak * e.w;
    }
    *reinterpret_cast<float4*>(&mix[(size_t)R * D_DIM + lane * 4]) = accv;
}

// ---------------- small fp32 GEMM ----------------
__global__ void __launch_bounds__(256, 2) gemm_kernel(
    const float* __restrict__ A, const float* __restrict__ W,
    const float* __restrict__ bias, const float* __restrict__ aux,
    float* __restrict__ out, int trans, int epi)
{
    extern __shared__ float shf[];
    float* Wsh = shf;
    float* Ash = shf + 128 * PAD;
    const int tid = threadIdx.x;
    const int lane = tid & 31;
    const int wid = tid >> 5;
    const int rowbase = blockIdx.x * 32;

    if (!trans) {
        for (int i = tid; i < 128 * 32; i += 256) {
            int c = i >> 5, e4 = i & 31;
            float4 v = *reinterpret_cast<const float4*>(&W[c * D_DIM + e4 * 4]);
            *reinterpret_cast<float4*>(&Wsh[c * PAD + e4 * 4]) = v;
        }
    } else {
        for (int i = tid; i < 128 * 128; i += 256) {
            int e = i >> 7, c = i & 127;
            Wsh[c * PAD + e] = W[i];
        }
    }
    for (int i = tid; i < 32 * 32; i += 256) {
        int r = i >> 5, d4 = i & 31;
        float4 v = *reinterpret_cast<const float4*>(&A[(size_t)(rowbase + r) * D_DIM + d4 * 4]);
        *reinterpret_cast<float4*>(&Ash[r * PAD + d4 * 4]) = v;
    }
    __syncthreads();

    float acc[4][4];
#pragma unroll
    for (int j = 0; j < 4; j++)
#pragma unroll
        for (int k = 0; k < 4; k++) acc[j][k] = 0.0f;

    const float* abase = Ash + (wid * 4) * PAD;
    const float* wbase = Wsh + lane * PAD;
#pragma unroll 8
    for (int d = 0; d < D_DIM; d += 4) {
        float4 a0 = *reinterpret_cast<const float4*>(abase + 0 * PAD + d);
        float4 a1 = *reinterpret_cast<const float4*>(abase + 1 * PAD + d);
        float4 a2 = *reinterpret_cast<const float4*>(abase + 2 * PAD + d);
        float4 a3 = *reinterpret_cast<const float4*>(abase + 3 * PAD + d);
        float4 w0 = *reinterpret_cast<const float4*>(wbase + 0 * PAD + d);
        float4 w1 = *reinterpret_cast<const float4*>(wbase + 32 * PAD + d);
        float4 w2 = *reinterpret_cast<const float4*>(wbase + 64 * PAD + d);
        float4 w3 = *reinterpret_cast<const float4*>(wbase + 96 * PAD + d);
#define DO4(j, av) \
        acc[j][0] += av.x*w0.x + av.y*w0.y + av.z*w0.z + av.w*w0.w; \
        acc[j][1] += av.x*w1.x + av.y*w1.y + av.z*w1.z + av.w*w1.w; \
        acc[j][2] += av.x*w2.x + av.y*w2.y + av.z*w2.z + av.w*w2.w; \
        acc[j][3] += av.x*w3.x + av.y*w3.y + av.z*w3.z + av.w*w3.w;
        DO4(0, a0) DO4(1, a1) DO4(2, a2) DO4(3, a3)
#undef DO4
    }

#pragma unroll
    for (int j = 0; j < 4; j++) {
        int n = rowbase + wid * 4 + j;
#pragma unroll
        for (int k = 0; k < 4; k++) {
            int c = lane + 32 * k;
            float v = acc[j][k];
            if (bias) v += bias[c];
            if (epi == 1) v = tanhf(v);
            else if (epi == 2) v += 0.1f * aux[(size_t)n * D_DIM + c];
            out[(size_t)n * D_DIM + c] = v;
        }
    }
}

// ---------------- fusion column softmax (two branches in one launch) ----------------
__global__ void colinit_kernel(unsigned* cmax, float* csum) {
    int i = threadIdx.x;
    if (i < 2 * D_DIM) { cmax[i] = f2key(-1e30f); csum[i] = 0.0f; }
}
__global__ void __launch_bounds__(128) colmax_kernel(const float* __restrict__ t, unsigned* __restrict__ cmax) {
    int d = threadIdx.x;
    int r0 = blockIdx.x * 128;
    int br = (r0 >= N_CNT) ? D_DIM : 0;
    float m = -1e30f;
    for (int r = r0; r < r0 + 128; r++) m = fmaxf(m, t[(size_t)r * D_DIM + d]);
    atomicMax(&cmax[br + d], f2key(m));
}
__global__ void __launch_bounds__(128) colsum_kernel(const float* __restrict__ t,
                                                     const unsigned* __restrict__ cmax,
                                                     float* __restrict__ csum) {
    int d = threadIdx.x;
    int r0 = blockIdx.x * 128;
    int br = (r0 >= N_CNT) ? D_DIM : 0;
    float mx = key2f(cmax[br + d]);
    float s = 0.0f;
    for (int r = r0; r < r0 + 128; r++) s += expf(t[(size_t)r * D_DIM + d] - mx);
    atomicAdd(&csum[br + d], s);
}
__global__ void fusion_kernel(const float* __restrict__ t1, const float* __restrict__ t2,
                              const unsigned* __restrict__ cmax, const float* __restrict__ csum,
                              const float* __restrict__ all, const float* __restrict__ atten,
                              float* __restrict__ out, int n) {
    int i = blockIdx.x * blockDim.x + threadIdx.x;
    if (i >= n) return;
    int d = i & (D_DIM - 1);
    float w1 = expf(t1[i] - key2f(cmax[d]))         / csum[d];
    float w2 = expf(t2[i] - key2f(cmax[D_DIM + d])) / csum[D_DIM + d];
    out[i] = w1 * all[i] + w2 * atten[i];
}

// ---------------- launch ----------------
extern "C" void kernel_launch(void* const* d_in, const int* in_sizes, int n_in,
                              void* d_out, int out_size) {
    const float* user = (const float*)d_in[0];
    const float* item = (const float*)d_in[1];
    const int*   rows = (const int*)d_in[2];
    const int*   cols = (const int*)d_in[3];
    const float* vals = (const float*)d_in[4];
    const float* wq   = (const float*)d_in[5];
    const float* bq   = (const float*)d_in[6];
    const float* wk   = (const float*)d_in[7];
    const float* wv   = (const float*)d_in[9];
    const float* bv   = (const float*)d_in[10];
    const float* fw   = (const float*)d_in[11];
    const float* fb   = (const float*)d_in[12];

    const int ND = N_CNT * D_DIM;
    const int SMEM = (128 * PAD + 32 * PAD) * 4;
    cudaFuncSetAttribute(gemm_kernel, cudaFuncAttributeMaxDynamicSharedMemorySize, SMEM);
    cudaFuncSetAttribute(simgemm_kernel, cudaFuncAttributeMaxDynamicSharedMemorySize, GEMM_SMEM);

    float *bufA, *bufB, *ego, *qbuf, *qkb, *mixb, *csum, *eval, *scalef, *muf, *cvec;
    __half *egoh, *simp;
    int *cand, *rowstart, *cursor, *ecol;
    unsigned *cmax, *skey;
    cudaGetSymbolAddress((void**)&bufA, g_bufA);
    cudaGetSymbolAddress((void**)&bufB, g_bufB);
    cudaGetSymbolAddress((void**)&ego,  g_ego);
    cudaGetSymbolAddress((void**)&qbuf, g_q);
    cudaGetSymbolAddress((void**)&qkb,  g_qk);
    cudaGetSymbolAddress((void**)&mixb, g_mix);
    cudaGetSymbolAddress((void**)&egoh, g_egoh);
    cudaGetSymbolAddress((void**)&simp, g_sim);
    cudaGetSymbolAddress((void**)&cand, g_cand);
    cudaGetSymbolAddress((void**)&cmax, g_cmax);
    cudaGetSymbolAddress((void**)&csum, g_csum);
    cudaGetSymbolAddress((void**)&skey, g_skey);
    cudaGetSymbolAddress((void**)&scalef, g_scale);
    cudaGetSymbolAddress((void**)&muf, g_mu);
    cudaGetSymbolAddress((void**)&cvec, g_cvec);
    cudaGetSymbolAddress((void**)&rowstart, g_rowstart);
    cudaGetSymbolAddress((void**)&cursor, g_cursor);
    cudaGetSymbolAddress((void**)&ecol, g_ecol);
    cudaGetSymbolAddress((void**)&eval, g_eval);

    float* outAll = (float*)d_out;
    float* outAtt = outAll + ND;
    float* outFus = outAll + 2 * ND;
    float* tbuf = (float*)simp;   // 2*ND fp32 scratch inside dead sim buffer

    const int ZB = ND / 256;
    const int EB = E_CNT / 256;
    const int RB = (N_CNT * 32) / 256;

    // CSR build (atomic-free SpMM afterwards)
    zero_int_kernel<<<N_CNT / 256, 256>>>(cursor, N_CNT);
    hist_kernel<<<EB, 256>>>(rows, cursor);
    scan_kernel<<<1, 512>>>(cursor, rowstart, cursor);
    scatter_kernel<<<EB, 256>>>(rows, cols, vals, cursor, ecol, eval);

    // 3 SpMM layers
    spmm_csr_kernel<<<RB, 256>>>(user, item, rowstart, ecol, eval, bufA);
    spmm_csr_kernel<<<RB, 256>>>(bufA, bufA + U_CNT * D_DIM, rowstart, ecol, eval, bufB);
    spmm_csr_kernel<<<RB, 256>>>(bufB, bufB + U_CNT * D_DIM, rowstart, ecol, eval, ego);
    mean3_kernel<<<ZB, 256>>>(bufA, bufB, ego, outAll, ND);

    // row-offset stats (+ fused fp16 convert)
    zero_int_kernel<<<1, 32>>>((int*)skey, 2);
    zero_int_kernel<<<1, 128>>>((int*)muf, D_DIM);
    colmean_kernel<<<N_CNT / 128, 128>>>(ego, muf);
    rowdot_kernel<<<RB, 256>>>(ego, muf, cvec, skey, egoh);
    scale2_kernel<<<1, 1>>>(skey, scalef);

    // symmetric offset-removed fp16 sim GEMM -> top-64 scan
    simgemm_kernel<<<dim3(N_CNT / 128, N_CNT / 128), 256, GEMM_SMEM>>>(egoh, simp, scalef, cvec);
    select_kernel<<<RB, 256>>>(simp, cand);

    // qk = ego @ (wq^T wk) + bq@wk   (independent of selection -> before fused kernel)
    wqk_kernel<<<128, 128>>>(wq, wk, bq, qbuf);
    gemm_kernel<<<N_CNT / 32, 256, SMEM>>>(ego, qbuf, qbuf + D_DIM * D_DIM, nullptr, qkb, 1, 0);

    // fused fp32 rescore -> exact top-32 -> attention mix
    rescore_attn_kernel<<<N_CNT / 8, 256>>>(ego, qkb, cand, mixb);

    // atten_embed = mix@wv^T + bv + 0.1*ego
    gemm_kernel<<<N_CNT / 32, 256, SMEM>>>(mixb, wv, bv, ego, outAtt, 0, 2);

    // fusion gating: single 2N-row GEMM into tbuf (sim scratch is dead now)
    gemm_kernel<<<2 * N_CNT / 32, 256, SMEM>>>(outAll, fw, fb, nullptr, tbuf, 0, 1);
    colinit_kernel<<<1, 256>>>(cmax, csum);
    colmax_kernel<<<2 * N_CNT / 128, 128>>>(tbuf, cmax);
    colsum_kernel<<<2 * N_CNT / 128, 128>>>(tbuf, cmax, csum);
    fusion_kernel<<<ZB, 256>>>(tbuf, tbuf + ND, cmax, csum, outAll, outAtt, outFus, ND);
}